// round 8
// baseline (speedup 1.0000x reference)
#include <cuda_runtime.h>
#include <cuda_fp16.h>
#include <math.h>
#include <stdint.h>

#define DIM 128
#define NV 50000
#define NL 100000
#define NC 210000
#define ECNT 300000
#define EFNT 100000
#define ENNT 200000
#define ETOT 600000
#define ROUNDS 8
#define KAGG 416   // 384 sums + 3 deg + 29 zero pad (multiple of 32)

typedef __half fp16;
typedef __half2 fp162;

// ------------------------- static device scratch -------------------------
__device__ fp16  g_Lh0[(size_t)NL * DIM];
__device__ fp16  g_Lh1[(size_t)NL * DIM];
__device__ float g_Lc [(size_t)NL * DIM];
__device__ fp16  g_Ch0[(size_t)NC * DIM];
__device__ fp16  g_Ch1[(size_t)NC * DIM];
__device__ float g_Cc [(size_t)NC * DIM];
__device__ fp16  g_MSG[(size_t)NC * DIM];
__device__ fp16  g_G  [(size_t)NL * 384];
__device__ fp16  g_AGG[(size_t)NL * KAGG];
__device__ float g_Weff[6 * DIM * DIM];
__device__ float g_beff[6 * DIM];
__device__ fp16  g_WgatC[384 * DIM];
__device__ fp16  g_WcatL[DIM * KAGG];
__device__ fp16  g_WC[512 * 256];
__device__ float g_bC[512];
__device__ fp16  g_WL[512 * 384];
__device__ float g_bL[512];
__device__ fp16  g_W1[128 * 256];
__device__ fp16  g_W2[128 * 128];
__device__ float g_zero[512];
// CSR scratch
__device__ int g_offsLC[NC + 1];
__device__ int g_offsCL[NL + 1];
__device__ int g_payLC[ETOT];
__device__ int g_payCL[ETOT];
__device__ int g_cnt[NC];
__device__ int g_cur[NC];
__device__ int g_exsc[NC];
__device__ int g_blksum[256];

__device__ __forceinline__ float sigmoidf_(float x) { return 1.0f / (1.0f + __expf(-x)); }

// ------------------------- weff precompute (fp32) -------------------------
__global__ void compute_weff_kernel(const float* __restrict__ mha_in_w,
                                    const float* __restrict__ mha_in_b,
                                    const float* __restrict__ mha_out_w,
                                    const float* __restrict__ mha_out_b,
                                    float* __restrict__ Weff,
                                    float* __restrict__ beff) {
    int o = blockIdx.x, t = blockIdx.y, v = threadIdx.x;
    const float* Wo = mha_out_w + (size_t)t * DIM * DIM + (size_t)o * DIM;
    const float* Wv = mha_in_w + (size_t)t * 3 * DIM * DIM + (size_t)2 * DIM * DIM;
    float acc = 0.0f;
#pragma unroll 8
    for (int j = 0; j < DIM; j++) acc += Wo[j] * Wv[(size_t)j * DIM + v];
    Weff[((size_t)t * DIM + o) * DIM + v] = acc;
    if (v == 0) {
        const float* bv = mha_in_b + t * 3 * DIM + 2 * DIM;
        float s = 0.0f;
        for (int j = 0; j < DIM; j++) s += Wo[j] * bv[j];
        beff[t * DIM + o] = s + mha_out_b[t * DIM + o];
    }
}

__global__ void prep_wgat_kernel(const float* __restrict__ Weff, fp16* __restrict__ Wg) {
    int n = blockIdx.x, k = threadIdx.x;
    Wg[(size_t)n * 128 + k] = __float2half_rn(Weff[(size_t)n * 128 + k]);
}

__global__ void prep_wcatL_kernel(const float* __restrict__ Weff, const float* __restrict__ beff,
                                  fp16* __restrict__ Wc) {
    int n = blockIdx.x, k = threadIdx.x;   // 0..415
    float v;
    if (k < 384) {
        int t = k >> 7, j = k & 127;
        v = Weff[(((size_t)(3 + t)) * DIM + n) * DIM + j];
    } else if (k < 387) {
        v = beff[(3 + (k - 384)) * DIM + n];
    } else v = 0.0f;
    Wc[(size_t)n * KAGG + k] = __float2half_rn(v);
}

__global__ void prep_lstm_kernel(const float* __restrict__ wih, const float* __restrict__ whh,
                                 const float* __restrict__ bih, const float* __restrict__ bhh,
                                 fp16* __restrict__ Wd, float* __restrict__ bd, int KX) {
    int n = blockIdx.x, k = threadIdx.x;
    int K = KX + 128;
    int orig = (n & 3) * 128 + (n >> 2);
    float v = (k < KX) ? wih[(size_t)orig * KX + k] : whh[(size_t)orig * 128 + (k - KX)];
    Wd[(size_t)n * K + k] = __float2half_rn(v);
    if (k == 0) bd[n] = bih[orig] + bhh[orig];
}

__global__ void prep_mlp_kernel(const float* __restrict__ w1, const float* __restrict__ w2,
                                fp16* __restrict__ W1r, fp16* __restrict__ W2r) {
    int i = blockIdx.x * blockDim.x + threadIdx.x;
    if (i < 128 * 256) W1r[i] = __float2half_rn(w1[i]);
    if (i < 128 * 128) W2r[i] = __float2half_rn(w2[i]);
}

__global__ void init_state_kernel(const float* __restrict__ lw, const float* __restrict__ lb,
                                  const float* __restrict__ cw, const float* __restrict__ cb,
                                  fp16* __restrict__ Lh, float* __restrict__ Lc,
                                  fp16* __restrict__ Ch, float* __restrict__ Cc) {
    size_t idx = (size_t)blockIdx.x * blockDim.x + threadIdx.x;
    int j = (int)(idx & (DIM - 1));
    if (idx < (size_t)NL * DIM) { Lh[idx] = __float2half_rn(lw[j] + lb[j]); Lc[idx] = 0.0f; }
    if (idx < (size_t)NC * DIM) { Ch[idx] = __float2half_rn(cw[j] + cb[j]); Cc[idx] = 0.0f; }
}

// ------------------------- CSR build -------------------------
__global__ void zero_int_kernel(int* __restrict__ p, int n) {
    int i = blockIdx.x * blockDim.x + threadIdx.x;
    if (i < n) p[i] = 0;
}
__global__ void hist_kernel(const int* __restrict__ dst, int E, int* __restrict__ cnt) {
    int e = blockIdx.x * blockDim.x + threadIdx.x;
    if (e < E) atomicAdd(&cnt[dst[e]], 1);
}
__global__ void scanA_kernel(const int* __restrict__ cnt, int* __restrict__ exsc,
                             int* __restrict__ blksum, int n) {
    __shared__ int sm[1024];
    int tid = threadIdx.x;
    int i = blockIdx.x * 1024 + tid;
    int v = (i < n) ? cnt[i] : 0;
    sm[tid] = v;
    __syncthreads();
    for (int o = 1; o < 1024; o <<= 1) {
        int t = (tid >= o) ? sm[tid - o] : 0;
        __syncthreads();
        sm[tid] += t;
        __syncthreads();
    }
    if (i < n) exsc[i] = sm[tid] - v;
    if (tid == 1023) blksum[blockIdx.x] = sm[1023];
}
__global__ void scanB_kernel(int* __restrict__ blksum, int nb) {
    if (threadIdx.x == 0 && blockIdx.x == 0) {
        int s = 0;
        for (int b = 0; b < nb; b++) { int t = blksum[b]; blksum[b] = s; s += t; }
    }
}
__global__ void scanC_kernel(const int* __restrict__ exsc, const int* __restrict__ blksum,
                             int* __restrict__ offs, int n, int E) {
    int i = blockIdx.x * blockDim.x + threadIdx.x;
    if (i < n) offs[i] = exsc[i] + blksum[i >> 10];
    if (i == 0) offs[n] = E;
}
__global__ void fill_csr_kernel(const int* __restrict__ src, const int* __restrict__ dst, int E,
                                int type, const int* __restrict__ offs, int* __restrict__ cur,
                                int* __restrict__ pay) {
    int e = blockIdx.x * blockDim.x + threadIdx.x;
    if (e < E) {
        int d = dst[e];
        int pos = offs[d] + atomicAdd(&cur[d], 1);
        pay[pos] = src[e] | (type << 28);
    }
}

// ------------------------- aggregation kernels -------------------------
__global__ void aggL2C_kernel(const int* __restrict__ pay, const int* __restrict__ offs,
                              const fp16* __restrict__ G, const float* __restrict__ beff,
                              fp16* __restrict__ MSG, int ndst) {
    int w = (blockIdx.x * blockDim.x + threadIdx.x) >> 5;
    int lane = threadIdx.x & 31;
    if (w >= ndst) return;
    int beg = offs[w], end = offs[w + 1];
    float a0 = 0.f, a1 = 0.f, a2 = 0.f, a3 = 0.f;
    int d0 = 0, d1 = 0, d2 = 0;
    int j = lane * 4;
    for (int i = beg; i < end; i++) {
        unsigned p = (unsigned)__ldg(pay + i);
        int s = (int)(p & 0x0FFFFFFFu);
        int t = (int)(p >> 28);
        const fp162* src = (const fp162*)(G + (size_t)s * 384 + t * 128 + j);
        float2 f0 = __half22float2(src[0]);
        float2 f1 = __half22float2(src[1]);
        a0 += f0.x; a1 += f0.y; a2 += f1.x; a3 += f1.y;
        d0 += (t == 0); d1 += (t == 1); d2 += (t == 2);
    }
    float fd0 = (float)d0, fd1 = (float)d1, fd2 = (float)d2;
    a0 += fd0 * beff[j + 0] + fd1 * beff[128 + j + 0] + fd2 * beff[256 + j + 0];
    a1 += fd0 * beff[j + 1] + fd1 * beff[128 + j + 1] + fd2 * beff[256 + j + 1];
    a2 += fd0 * beff[j + 2] + fd1 * beff[128 + j + 2] + fd2 * beff[256 + j + 2];
    a3 += fd0 * beff[j + 3] + fd1 * beff[128 + j + 3] + fd2 * beff[256 + j + 3];
    fp162* dst = (fp162*)(MSG + (size_t)w * 128 + j);
    dst[0] = __floats2half2_rn(a0, a1);
    dst[1] = __floats2half2_rn(a2, a3);
}

__global__ void aggC2L_kernel(const int* __restrict__ pay, const int* __restrict__ offs,
                              const fp16* __restrict__ H, fp16* __restrict__ AGG, int ndst) {
    int w = (blockIdx.x * blockDim.x + threadIdx.x) >> 5;
    int lane = threadIdx.x & 31;
    if (w >= ndst) return;
    int beg = offs[w], end = offs[w + 1];
    float a[3][4];
#pragma unroll
    for (int t = 0; t < 3; t++)
#pragma unroll
        for (int q = 0; q < 4; q++) a[t][q] = 0.f;
    int d0 = 0, d1 = 0, d2 = 0;
    int j = lane * 4;
    for (int i = beg; i < end; i++) {
        unsigned p = (unsigned)__ldg(pay + i);
        int s = (int)(p & 0x0FFFFFFFu);
        int t = (int)(p >> 28);
        const fp162* src = (const fp162*)(H + (size_t)s * 128 + j);
        float2 f0 = __half22float2(src[0]);
        float2 f1 = __half22float2(src[1]);
        if (t == 0)      { a[0][0] += f0.x; a[0][1] += f0.y; a[0][2] += f1.x; a[0][3] += f1.y; d0++; }
        else if (t == 1) { a[1][0] += f0.x; a[1][1] += f0.y; a[1][2] += f1.x; a[1][3] += f1.y; d1++; }
        else             { a[2][0] += f0.x; a[2][1] += f0.y; a[2][2] += f1.x; a[2][3] += f1.y; d2++; }
    }
    size_t base = (size_t)w * KAGG;
#pragma unroll
    for (int t = 0; t < 3; t++) {
        fp162* dst = (fp162*)(AGG + base + t * 128 + j);
        dst[0] = __floats2half2_rn(a[t][0], a[t][1]);
        dst[1] = __floats2half2_rn(a[t][2], a[t][3]);
    }
    if (lane < 8) {
        fp162* dst = (fp162*)(AGG + base + 384 + lane * 4);
        fp162 z = __floats2half2_rn(0.f, 0.f);
        dst[0] = z; dst[1] = z;
    }
    __syncwarp();
    if (lane == 0) {
        AGG[base + 384] = __float2half_rn((float)d0);
        AGG[base + 385] = __float2half_rn((float)d1);
        AGG[base + 386] = __float2half_rn((float)d2);
    }
}

// ------------------------- cp.async helpers -------------------------
__device__ __forceinline__ void cp16(uint32_t dst, const void* src, int sz) {
    asm volatile("cp.async.cg.shared.global [%0], [%1], 16, %2;" :: "r"(dst), "l"(src), "r"(sz));
}
__device__ __forceinline__ void cp_commit() { asm volatile("cp.async.commit_group;"); }
__device__ __forceinline__ void cp_wait0() { asm volatile("cp.async.wait_group 0;"); }
__device__ __forceinline__ void cp_wait1() { asm volatile("cp.async.wait_group 1;"); }

__device__ __forceinline__ void ldm_x4(uint32_t addr, uint32_t& r0, uint32_t& r1, uint32_t& r2, uint32_t& r3) {
    asm volatile("ldmatrix.sync.aligned.m8n8.x4.shared.b16 {%0,%1,%2,%3}, [%4];"
                 : "=r"(r0), "=r"(r1), "=r"(r2), "=r"(r3) : "r"(addr));
}

#define MMA16(d, a, b)                                                                             \
    asm volatile("mma.sync.aligned.m16n8k16.row.col.f32.f16.f16.f32 "                             \
                 "{%0,%1,%2,%3},{%4,%5,%6,%7},{%8,%9},{%0,%1,%2,%3};"                             \
                 : "+f"(d[0]), "+f"(d[1]), "+f"(d[2]), "+f"(d[3])                                  \
                 : "r"(a[0]), "r"(a[1]), "r"(a[2]), "r"(a[3]), "r"(b[0]), "r"(b[1]))

// smem geometry (halves)
#define MM_STR 40
#define MM_STAGE_HALVES (128 * MM_STR)
#define MM_SMEM_HALVES  (3 * 2 * MM_STAGE_HALVES)
#define MM_SMEM_BYTES   (MM_SMEM_HALVES * 2)             // 61440

// ------------------------- unified fp16 tensor-core GEMM -------------------------
// 128 threads (4 warps), warp tile 64x64: CTA tile 128x128, acc 4x8x4 per thread.
// Y[M,N] = X[M,K] @ W[N,K]^T (+ bias)
// XMODE: 0 plain (stride=K), 1 [MSG|Ch], 2 [MSG|flip|H], 3 [L[:NV]|L[NV:]]
// EPI:   0 bias-store, 1 bias-relu-store, 2 fused LSTM cell (gate-permuted weights)
// GSWAP: 1 -> (m,n)=(by,bx): n-blocks schedule-adjacent for L2 X reuse
template <int XMODE, int EPI, int K, int GSWAP>
__global__ void __launch_bounds__(128, 2) mm_kernel(
    const fp16* __restrict__ X0, const fp16* __restrict__ X1,
    const fp16* __restrict__ W, const float* __restrict__ bias,
    fp16* __restrict__ Y, int ldY,
    const float* __restrict__ Cold, fp16* __restrict__ Hnew, float* __restrict__ Cnew,
    int M) {
    extern __shared__ __align__(16) fp16 smraw[];
    fp16* xs = smraw;                          // [3][128][MM_STR]
    fp16* ws = smraw + 3 * MM_STAGE_HALVES;    // [3][128][MM_STR]
    const int tid = threadIdx.x;
    const int lane = tid & 31, warp = tid >> 5;
    const int wm = warp & 1, wn = warp >> 1;   // 2x2 warp grid, 64x64 tiles
    const int mblk = GSWAP ? blockIdx.y : blockIdx.x;
    const int nblk = GSWAP ? blockIdx.x : blockIdx.y;
    const int row0 = mblk * 128, n0 = nblk * 128;
    const uint32_t xs_u = (uint32_t)__cvta_generic_to_shared(xs);
    const uint32_t ws_u = (uint32_t)__cvta_generic_to_shared(ws);

    float acc[4][8][4];
#pragma unroll
    for (int a = 0; a < 4; a++)
#pragma unroll
        for (int b = 0; b < 8; b++)
#pragma unroll
            for (int c = 0; c < 4; c++) acc[a][b][c] = 0.0f;

    auto load_tiles = [&](int it, int buf) {
        int kb = it * 32;
        uint32_t xbase = xs_u + (uint32_t)(buf * MM_STAGE_HALVES * 2);
        uint32_t wbase = ws_u + (uint32_t)(buf * MM_STAGE_HALVES * 2);
        // X tile: 128 rows x 32 halves = 512 x 16B chunks; 4 per thread
#pragma unroll
        for (int q = 0; q < 4; q++) {
            int chunk = tid + 128 * q;
            int r = chunk >> 2, cc = chunk & 3;
            int gr = row0 + r;
            int grc = gr < M ? gr : (M - 1);
            int gk = kb + cc * 8;
            const fp16* src;
            if (XMODE == 0) {
                src = X0 + (size_t)grc * K + gk;
            } else if (XMODE == 1) {
                src = (gk < 128) ? X0 + (size_t)grc * 128 + gk
                                 : X1 + (size_t)grc * 128 + (gk - 128);
            } else if (XMODE == 2) {
                if (gk < 128) src = X0 + (size_t)grc * 128 + gk;
                else if (gk < 256) {
                    int fr = (grc < NV) ? grc + NV : grc - NV;
                    src = X1 + (size_t)fr * 128 + (gk - 128);
                } else src = X1 + (size_t)grc * 128 + (gk - 256);
            } else {  // XMODE 3
                src = (gk < 128) ? X0 + (size_t)grc * 128 + gk
                                 : X0 + (size_t)(grc + NV) * 128 + (gk - 128);
            }
            cp16(xbase + (uint32_t)((r * MM_STR + cc * 8) * 2), src, gr < M ? 16 : 0);
        }
#pragma unroll
        for (int q = 0; q < 4; q++) {
            int chunk = tid + 128 * q;
            int n = chunk >> 2, cc = chunk & 3;
            const fp16* src = W + (size_t)(n0 + n) * K + kb + cc * 8;
            cp16(wbase + (uint32_t)((n * MM_STR + cc * 8) * 2), src, 16);
        }
        cp_commit();
    };

    auto compute = [&](int buf) {
        uint32_t xbase = xs_u + (uint32_t)(buf * MM_STAGE_HALVES * 2);
        uint32_t wbase = ws_u + (uint32_t)(buf * MM_STAGE_HALVES * 2);
#pragma unroll
        for (int ks = 0; ks < 2; ks++) {
            int coloff = ks * 16 + ((lane >> 4) & 1) * 8;
            uint32_t afrag[4][4];
#pragma unroll
            for (int mt = 0; mt < 4; mt++) {
                int r = wm * 64 + mt * 16 + (lane & 15);
                uint32_t addr = xbase + (uint32_t)((r * MM_STR + coloff) * 2);
                ldm_x4(addr, afrag[mt][0], afrag[mt][1], afrag[mt][2], afrag[mt][3]);
            }
            uint32_t bfrag[8][2];
#pragma unroll
            for (int p = 0; p < 4; p++) {
                int n = wn * 64 + p * 16 + (lane & 15);
                uint32_t addr = wbase + (uint32_t)((n * MM_STR + coloff) * 2);
                uint32_t r0, r1, r2, r3;
                ldm_x4(addr, r0, r1, r2, r3);
                bfrag[2 * p][0] = r0; bfrag[2 * p][1] = r2;
                bfrag[2 * p + 1][0] = r1; bfrag[2 * p + 1][1] = r3;
            }
#pragma unroll
            for (int mt = 0; mt < 4; mt++)
#pragma unroll
                for (int nt = 0; nt < 8; nt++) MMA16(acc[mt][nt], afrag[mt], bfrag[nt]);
        }
    };

    constexpr int ITERS = K / 32;
    load_tiles(0, 0);
    load_tiles(1, 1);
    for (int it = 0; it < ITERS; it++) {
        if (it + 1 < ITERS) cp_wait1(); else cp_wait0();
        __syncthreads();
        if (it + 2 < ITERS) load_tiles(it + 2, (it + 2) % 3);
        compute(it % 3);
    }
    __syncthreads();   // protect epilogue smem reuse from lagging warps

    if (EPI == 0 || EPI == 1) {
#pragma unroll
        for (int mt = 0; mt < 4; mt++) {
#pragma unroll
            for (int nt = 0; nt < 8; nt++) {
                int gr0 = row0 + wm * 64 + mt * 16 + (lane >> 2);
                int col = n0 + wn * 64 + nt * 8 + 2 * (lane & 3);
                float b0v = __ldg(bias + col), b1v = __ldg(bias + col + 1);
                float v0 = acc[mt][nt][0] + b0v, v1 = acc[mt][nt][1] + b1v;
                float v2 = acc[mt][nt][2] + b0v, v3 = acc[mt][nt][3] + b1v;
                if (EPI == 1) {
                    v0 = fmaxf(v0, 0.f); v1 = fmaxf(v1, 0.f);
                    v2 = fmaxf(v2, 0.f); v3 = fmaxf(v3, 0.f);
                }
                if (gr0 < M)
                    *(fp162*)(Y + (size_t)gr0 * ldY + col) = __floats2half2_rn(v0, v1);
                if (gr0 + 8 < M)
                    *(fp162*)(Y + (size_t)(gr0 + 8) * ldY + col) = __floats2half2_rn(v2, v3);
            }
        }
    } else {
        // fused LSTM epilogue; this block handles kk in [nblk*32, +32)
        const int kk0 = nblk * 32;
        float* cs = (float*)smraw;        // [128][33]
        float* hs = cs + 128 * 33;        // [128][33]
        for (int i = tid; i < 1024; i += 128) {
            int r = i >> 3, c = (i & 7) * 4;
            int gr = row0 + r;
            if (gr < M) {
                float4 v = *(const float4*)(Cold + (size_t)gr * 128 + kk0 + c);
                cs[r * 33 + c + 0] = v.x; cs[r * 33 + c + 1] = v.y;
                cs[r * 33 + c + 2] = v.z; cs[r * 33 + c + 3] = v.w;
            }
        }
        __syncthreads();
        const int odd = lane & 1;
#pragma unroll
        for (int nt = 0; nt < 8; nt++) {
            int colp = wn * 64 + nt * 8 + 2 * (lane & 3);
            float b0v = __ldg(bias + n0 + colp), b1v = __ldg(bias + n0 + colp + 1);
            int kkl = colp >> 2;
#pragma unroll
            for (int mt = 0; mt < 4; mt++) {
                float c0 = acc[mt][nt][0] + b0v, c1 = acc[mt][nt][1] + b1v;
                float c2 = acc[mt][nt][2] + b0v, c3 = acc[mt][nt][3] + b1v;
                float x0 = __shfl_xor_sync(0xffffffffu, c0, 1);
                float x1 = __shfl_xor_sync(0xffffffffu, c1, 1);
                float x2 = __shfl_xor_sync(0xffffffffu, c2, 1);
                float x3 = __shfl_xor_sync(0xffffffffu, c3, 1);
                float gi = odd ? x2 : c0;
                float gf = odd ? x3 : c1;
                float gg = odd ? c2 : x0;
                float go = odd ? c3 : x1;
                int rloc = wm * 64 + mt * 16 + (lane >> 2) + odd * 8;
                float cold = cs[rloc * 33 + kkl];
                float c2v = sigmoidf_(gf) * cold + sigmoidf_(gi) * tanhf(gg);
                float h = sigmoidf_(go) * tanhf(c2v);
                cs[rloc * 33 + kkl] = c2v;
                hs[rloc * 33 + kkl] = h;
            }
        }
        __syncthreads();
        for (int i = tid; i < 1024; i += 128) {
            int r = i >> 3, c = (i & 7) * 4;
            int gr = row0 + r;
            if (gr < M) {
                float4 cv = make_float4(cs[r * 33 + c], cs[r * 33 + c + 1],
                                        cs[r * 33 + c + 2], cs[r * 33 + c + 3]);
                *(float4*)(Cnew + (size_t)gr * 128 + kk0 + c) = cv;
                fp162* hp = (fp162*)(Hnew + (size_t)gr * 128 + kk0 + c);
                hp[0] = __floats2half2_rn(hs[r * 33 + c], hs[r * 33 + c + 1]);
                hp[1] = __floats2half2_rn(hs[r * 33 + c + 2], hs[r * 33 + c + 3]);
            }
        }
    }
}

// ------------------------- final vote -------------------------
__global__ void vote_kernel(const fp16* __restrict__ H2, const float* __restrict__ w3,
                            const float* __restrict__ b3, float* __restrict__ out, int M) {
    int w = (blockIdx.x * blockDim.x + threadIdx.x) >> 5;
    int lane = threadIdx.x & 31;
    if (w < M) {
        float s = 0.0f;
#pragma unroll
        for (int q = 0; q < 4; q++) {
            int j = lane + 32 * q;
            s += __half2float(H2[(size_t)w * 128 + j]) * __ldg(w3 + j);
        }
#pragma unroll
        for (int o = 16; o > 0; o >>= 1) s += __shfl_xor_sync(0xffffffffu, s, o);
        if (lane == 0) out[w] = s + b3[0];
    }
}

// ------------------------- host orchestration -------------------------
static void build_csr(const int* src0, const int* dst0, int E0,
                      const int* src1, const int* dst1, int E1,
                      const int* src2, const int* dst2, int E2,
                      int ndst, int* offs, int* pay,
                      int* cnt, int* cur, int* exsc, int* blksum) {
    zero_int_kernel<<<(ndst + 255) / 256, 256>>>(cnt, ndst);
    hist_kernel<<<(E0 + 255) / 256, 256>>>(dst0, E0, cnt);
    hist_kernel<<<(E1 + 255) / 256, 256>>>(dst1, E1, cnt);
    hist_kernel<<<(E2 + 255) / 256, 256>>>(dst2, E2, cnt);
    int nb = (ndst + 1023) / 1024;
    scanA_kernel<<<nb, 1024>>>(cnt, exsc, blksum, ndst);
    scanB_kernel<<<1, 32>>>(blksum, nb);
    scanC_kernel<<<(ndst + 255) / 256, 256>>>(exsc, blksum, offs, ndst, E0 + E1 + E2);
    zero_int_kernel<<<(ndst + 255) / 256, 256>>>(cur, ndst);
    fill_csr_kernel<<<(E0 + 255) / 256, 256>>>(src0, dst0, E0, 0, offs, cur, pay);
    fill_csr_kernel<<<(E1 + 255) / 256, 256>>>(src1, dst1, E1, 1, offs, cur, pay);
    fill_csr_kernel<<<(E2 + 255) / 256, 256>>>(src2, dst2, E2, 2, offs, cur, pay);
}

extern "C" void kernel_launch(void* const* d_in, const int* in_sizes, int n_in,
                              void* d_out, int out_size) {
    (void)in_sizes; (void)n_in; (void)out_size;
    const float* l_init_w   = (const float*)d_in[0];
    const float* l_init_b   = (const float*)d_in[1];
    const float* c_init_w   = (const float*)d_in[2];
    const float* c_init_b   = (const float*)d_in[3];
    const float* mha_in_w   = (const float*)d_in[4];
    const float* mha_in_b   = (const float*)d_in[5];
    const float* mha_out_w  = (const float*)d_in[6];
    const float* mha_out_b  = (const float*)d_in[7];
    const float* lstm_L_wih = (const float*)d_in[8];
    const float* lstm_L_whh = (const float*)d_in[9];
    const float* lstm_L_bih = (const float*)d_in[10];
    const float* lstm_L_bhh = (const float*)d_in[11];
    const float* lstm_C_wih = (const float*)d_in[12];
    const float* lstm_C_whh = (const float*)d_in[13];
    const float* lstm_C_bih = (const float*)d_in[14];
    const float* lstm_C_bhh = (const float*)d_in[15];
    const float* mlp_w1     = (const float*)d_in[16];
    const float* mlp_b1     = (const float*)d_in[17];
    const float* mlp_w2     = (const float*)d_in[18];
    const float* mlp_b2     = (const float*)d_in[19];
    const float* mlp_w3     = (const float*)d_in[20];
    const float* mlp_b3     = (const float*)d_in[21];
    const int* child_lit    = (const int*)d_in[22];
    const int* child_clause = (const int*)d_in[23];
    const int* fa_lit       = (const int*)d_in[24];
    const int* fa_clause    = (const int*)d_in[25];
    const int* nt_lit       = (const int*)d_in[26];
    const int* nt_clause    = (const int*)d_in[27];

    fp16 *Lh0, *Lh1, *Ch0, *Ch1, *MSG, *G, *AGG, *WgatC, *WcatL, *WC, *WL, *W1, *W2;
    float *Lc, *Cc, *Weff, *beff, *bC, *bL, *zeroB;
    int *offsLC, *offsCL, *payLC, *payCL, *cnt, *cur, *exsc, *blksum;
    cudaGetSymbolAddress((void**)&Lh0, g_Lh0);
    cudaGetSymbolAddress((void**)&Lh1, g_Lh1);
    cudaGetSymbolAddress((void**)&Lc,  g_Lc);
    cudaGetSymbolAddress((void**)&Ch0, g_Ch0);
    cudaGetSymbolAddress((void**)&Ch1, g_Ch1);
    cudaGetSymbolAddress((void**)&Cc,  g_Cc);
    cudaGetSymbolAddress((void**)&MSG, g_MSG);
    cudaGetSymbolAddress((void**)&G,   g_G);
    cudaGetSymbolAddress((void**)&AGG, g_AGG);
    cudaGetSymbolAddress((void**)&Weff, g_Weff);
    cudaGetSymbolAddress((void**)&beff, g_beff);
    cudaGetSymbolAddress((void**)&WgatC, g_WgatC);
    cudaGetSymbolAddress((void**)&WcatL, g_WcatL);
    cudaGetSymbolAddress((void**)&WC, g_WC);
    cudaGetSymbolAddress((void**)&bC, g_bC);
    cudaGetSymbolAddress((void**)&WL, g_WL);
    cudaGetSymbolAddress((void**)&bL, g_bL);
    cudaGetSymbolAddress((void**)&W1, g_W1);
    cudaGetSymbolAddress((void**)&W2, g_W2);
    cudaGetSymbolAddress((void**)&zeroB, g_zero);
    cudaGetSymbolAddress((void**)&offsLC, g_offsLC);
    cudaGetSymbolAddress((void**)&offsCL, g_offsCL);
    cudaGetSymbolAddress((void**)&payLC, g_payLC);
    cudaGetSymbolAddress((void**)&payCL, g_payCL);
    cudaGetSymbolAddress((void**)&cnt, g_cnt);
    cudaGetSymbolAddress((void**)&cur, g_cur);
    cudaGetSymbolAddress((void**)&exsc, g_exsc);
    cudaGetSymbolAddress((void**)&blksum, g_blksum);

    cudaFuncSetAttribute(mm_kernel<0, 0, 128, 1>, cudaFuncAttributeMaxDynamicSharedMemorySize, MM_SMEM_BYTES);
    cudaFuncSetAttribute(mm_kernel<1, 2, 256, 1>, cudaFuncAttributeMaxDynamicSharedMemorySize, MM_SMEM_BYTES);
    cudaFuncSetAttribute(mm_kernel<0, 0, KAGG, 0>, cudaFuncAttributeMaxDynamicSharedMemorySize, MM_SMEM_BYTES);
    cudaFuncSetAttribute(mm_kernel<2, 2, 384, 1>, cudaFuncAttributeMaxDynamicSharedMemorySize, MM_SMEM_BYTES);
    cudaFuncSetAttribute(mm_kernel<3, 1, 256, 0>, cudaFuncAttributeMaxDynamicSharedMemorySize, MM_SMEM_BYTES);
    cudaFuncSetAttribute(mm_kernel<0, 1, 128, 0>, cudaFuncAttributeMaxDynamicSharedMemorySize, MM_SMEM_BYTES);

    // ---- setup ----
    compute_weff_kernel<<<dim3(128, 6), 128>>>(mha_in_w, mha_in_b, mha_out_w, mha_out_b, Weff, beff);
    prep_wgat_kernel<<<384, 128>>>(Weff, WgatC);
    prep_wcatL_kernel<<<128, KAGG>>>(Weff, beff, WcatL);
    prep_lstm_kernel<<<512, 256>>>(lstm_C_wih, lstm_C_whh, lstm_C_bih, lstm_C_bhh, WC, bC, 128);
    prep_lstm_kernel<<<512, 384>>>(lstm_L_wih, lstm_L_whh, lstm_L_bih, lstm_L_bhh, WL, bL, 256);
    prep_mlp_kernel<<<(128 * 256 + 255) / 256, 256>>>(mlp_w1, mlp_w2, W1, W2);
    init_state_kernel<<<(int)(((size_t)NC * DIM + 255) / 256), 256>>>(
        l_init_w, l_init_b, c_init_w, c_init_b, Lh0, Lc, Ch0, Cc);

    build_csr(child_lit, child_clause, ECNT, fa_lit, fa_clause, EFNT, nt_lit, nt_clause, ENNT,
              NC, offsLC, payLC, cnt, cur, exsc, blksum);
    build_csr(child_clause, child_lit, ECNT, fa_clause, fa_lit, EFNT, nt_clause, nt_lit, ENNT,
              NL, offsCL, payCL, cnt, cur, exsc, blksum);

    fp16* Lcur = Lh0; fp16* Lnxt = Lh1;
    fp16* Ccur = Ch0; fp16* Cnxt = Ch1;

    const int GB_L = (NL + 127) / 128;   // 782
    const int GB_C = (NC + 127) / 128;   // 1641
    const int GB_V = (NV + 127) / 128;   // 391

    for (int r = 0; r < ROUNDS; r++) {
        // ---- L -> C: transform L (small side), gather-aggregate into MSG ----
        mm_kernel<0, 0, 128, 1><<<dim3(3, GB_L), 128, MM_SMEM_BYTES>>>(
            Lcur, nullptr, WgatC, zeroB, G, 384, nullptr, nullptr, nullptr, NL);
        aggL2C_kernel<<<(NC * 32 + 255) / 256, 256>>>(payLC, offsLC, G, beff, MSG, NC);
        mm_kernel<1, 2, 256, 1><<<dim3(4, GB_C), 128, MM_SMEM_BYTES>>>(
            MSG, Ccur, WC, bC, nullptr, 0, Cc, Cnxt, Cc, NC);
        { fp16* t = Ccur; Ccur = Cnxt; Cnxt = t; }

        // ---- C -> L: aggregate C (small dst side), then transform ----
        aggC2L_kernel<<<(NL * 32 + 255) / 256, 256>>>(payCL, offsCL, Ccur, AGG, NL);
        mm_kernel<0, 0, KAGG, 0><<<dim3(GB_L, 1), 128, MM_SMEM_BYTES>>>(
            AGG, nullptr, WcatL, zeroB, MSG, 128, nullptr, nullptr, nullptr, NL);
        mm_kernel<2, 2, 384, 1><<<dim3(4, GB_L), 128, MM_SMEM_BYTES>>>(
            MSG, Lcur, WL, bL, nullptr, 0, Lc, Lnxt, Lc, NL);
        { fp16* t = Lcur; Lcur = Lnxt; Lnxt = t; }
    }

    // ---- final MLP ----
    mm_kernel<3, 1, 256, 0><<<dim3(GB_V, 1), 128, MM_SMEM_BYTES>>>(
        Lcur, nullptr, W1, mlp_b1, G, 128, nullptr, nullptr, nullptr, NV);
    mm_kernel<0, 1, 128, 0><<<dim3(GB_V, 1), 128, MM_SMEM_BYTES>>>(
        G, nullptr, W2, mlp_b2, MSG, 128, nullptr, nullptr, nullptr, NV);
    vote_kernel<<<(NV * 32 + 255) / 256, 256>>>(MSG, mlp_w3, mlp_b3, (float*)d_out, NV);
}

// round 9
// speedup vs baseline: 1.2728x; 1.2728x over previous
#include <cuda_runtime.h>
#include <cuda_fp16.h>
#include <math.h>
#include <stdint.h>

#define DIM 128
#define NV 50000
#define NL 100000
#define NC 210000
#define ECNT 300000
#define EFNT 100000
#define ENNT 200000
#define ETOT 600000
#define ROUNDS 8
#define KAGG 416   // 384 sums + 3 deg + 29 zero pad (multiple of 32)

typedef __half fp16;
typedef __half2 fp162;

// ------------------------- static device scratch -------------------------
__device__ fp16  g_Lh0[(size_t)NL * DIM];
__device__ fp16  g_Lh1[(size_t)NL * DIM];
__device__ fp16  g_Lc [(size_t)NL * DIM];
__device__ fp16  g_Ch0[(size_t)NC * DIM];
__device__ fp16  g_Ch1[(size_t)NC * DIM];
__device__ fp16  g_Cc [(size_t)NC * DIM];
__device__ fp16  g_MSG[(size_t)NC * DIM];
__device__ fp16  g_G  [(size_t)NL * 384];
__device__ fp16  g_AGG[(size_t)NL * KAGG];
__device__ float g_Weff[6 * DIM * DIM];
__device__ float g_beff[6 * DIM];
__device__ fp16  g_WgatC[384 * DIM];
__device__ fp16  g_WcatL[DIM * KAGG];
__device__ fp16  g_WC[512 * 256];
__device__ float g_bC[512];
__device__ fp16  g_WL[512 * 384];
__device__ float g_bL[512];
__device__ fp16  g_W1[128 * 256];
__device__ fp16  g_W2[128 * 128];
__device__ float g_zero[512];
// CSR scratch
__device__ int g_offsLC[NC + 1];
__device__ int g_offsCL[NL + 1];
__device__ int g_payLC[ETOT];
__device__ int g_payCL[ETOT];
__device__ int g_cnt[NC];
__device__ int g_cur[NC];
__device__ int g_exsc[NC];
__device__ int g_blksum[256];

__device__ __forceinline__ float sigmoidf_(float x) { return 1.0f / (1.0f + __expf(-x)); }

// ------------------------- weff precompute (fp32) -------------------------
__global__ void compute_weff_kernel(const float* __restrict__ mha_in_w,
                                    const float* __restrict__ mha_in_b,
                                    const float* __restrict__ mha_out_w,
                                    const float* __restrict__ mha_out_b,
                                    float* __restrict__ Weff,
                                    float* __restrict__ beff) {
    int o = blockIdx.x, t = blockIdx.y, v = threadIdx.x;
    const float* Wo = mha_out_w + (size_t)t * DIM * DIM + (size_t)o * DIM;
    const float* Wv = mha_in_w + (size_t)t * 3 * DIM * DIM + (size_t)2 * DIM * DIM;
    float acc = 0.0f;
#pragma unroll 8
    for (int j = 0; j < DIM; j++) acc += Wo[j] * Wv[(size_t)j * DIM + v];
    Weff[((size_t)t * DIM + o) * DIM + v] = acc;
    if (v == 0) {
        const float* bv = mha_in_b + t * 3 * DIM + 2 * DIM;
        float s = 0.0f;
        for (int j = 0; j < DIM; j++) s += Wo[j] * bv[j];
        beff[t * DIM + o] = s + mha_out_b[t * DIM + o];
    }
}

__global__ void prep_wgat_kernel(const float* __restrict__ Weff, fp16* __restrict__ Wg) {
    int n = blockIdx.x, k = threadIdx.x;
    Wg[(size_t)n * 128 + k] = __float2half_rn(Weff[(size_t)n * 128 + k]);
}

__global__ void prep_wcatL_kernel(const float* __restrict__ Weff, const float* __restrict__ beff,
                                  fp16* __restrict__ Wc) {
    int n = blockIdx.x, k = threadIdx.x;   // 0..415
    float v;
    if (k < 384) {
        int t = k >> 7, j = k & 127;
        v = Weff[(((size_t)(3 + t)) * DIM + n) * DIM + j];
    } else if (k < 387) {
        v = beff[(3 + (k - 384)) * DIM + n];
    } else v = 0.0f;
    Wc[(size_t)n * KAGG + k] = __float2half_rn(v);
}

__global__ void prep_lstm_kernel(const float* __restrict__ wih, const float* __restrict__ whh,
                                 const float* __restrict__ bih, const float* __restrict__ bhh,
                                 fp16* __restrict__ Wd, float* __restrict__ bd, int KX) {
    int n = blockIdx.x, k = threadIdx.x;
    int K = KX + 128;
    int orig = (n & 3) * 128 + (n >> 2);
    float v = (k < KX) ? wih[(size_t)orig * KX + k] : whh[(size_t)orig * 128 + (k - KX)];
    Wd[(size_t)n * K + k] = __float2half_rn(v);
    if (k == 0) bd[n] = bih[orig] + bhh[orig];
}

__global__ void prep_mlp_kernel(const float* __restrict__ w1, const float* __restrict__ w2,
                                fp16* __restrict__ W1r, fp16* __restrict__ W2r) {
    int i = blockIdx.x * blockDim.x + threadIdx.x;
    if (i < 128 * 256) W1r[i] = __float2half_rn(w1[i]);
    if (i < 128 * 128) W2r[i] = __float2half_rn(w2[i]);
}

__global__ void init_state_kernel(const float* __restrict__ lw, const float* __restrict__ lb,
                                  const float* __restrict__ cw, const float* __restrict__ cb,
                                  fp16* __restrict__ Lh, fp16* __restrict__ Lc,
                                  fp16* __restrict__ Ch, fp16* __restrict__ Cc) {
    size_t idx = (size_t)blockIdx.x * blockDim.x + threadIdx.x;
    int j = (int)(idx & (DIM - 1));
    fp16 z = __float2half_rn(0.0f);
    if (idx < (size_t)NL * DIM) { Lh[idx] = __float2half_rn(lw[j] + lb[j]); Lc[idx] = z; }
    if (idx < (size_t)NC * DIM) { Ch[idx] = __float2half_rn(cw[j] + cb[j]); Cc[idx] = z; }
}

// ------------------------- CSR build -------------------------
__global__ void zero_int_kernel(int* __restrict__ p, int n) {
    int i = blockIdx.x * blockDim.x + threadIdx.x;
    if (i < n) p[i] = 0;
}
__global__ void hist_kernel(const int* __restrict__ dst, int E, int* __restrict__ cnt) {
    int e = blockIdx.x * blockDim.x + threadIdx.x;
    if (e < E) atomicAdd(&cnt[dst[e]], 1);
}
__global__ void scanA_kernel(const int* __restrict__ cnt, int* __restrict__ exsc,
                             int* __restrict__ blksum, int n) {
    __shared__ int sm[1024];
    int tid = threadIdx.x;
    int i = blockIdx.x * 1024 + tid;
    int v = (i < n) ? cnt[i] : 0;
    sm[tid] = v;
    __syncthreads();
    for (int o = 1; o < 1024; o <<= 1) {
        int t = (tid >= o) ? sm[tid - o] : 0;
        __syncthreads();
        sm[tid] += t;
        __syncthreads();
    }
    if (i < n) exsc[i] = sm[tid] - v;
    if (tid == 1023) blksum[blockIdx.x] = sm[1023];
}
__global__ void scanB_kernel(int* __restrict__ blksum, int nb) {
    if (threadIdx.x == 0 && blockIdx.x == 0) {
        int s = 0;
        for (int b = 0; b < nb; b++) { int t = blksum[b]; blksum[b] = s; s += t; }
    }
}
__global__ void scanC_kernel(const int* __restrict__ exsc, const int* __restrict__ blksum,
                             int* __restrict__ offs, int n, int E) {
    int i = blockIdx.x * blockDim.x + threadIdx.x;
    if (i < n) offs[i] = exsc[i] + blksum[i >> 10];
    if (i == 0) offs[n] = E;
}
__global__ void fill_csr_kernel(const int* __restrict__ src, const int* __restrict__ dst, int E,
                                int type, const int* __restrict__ offs, int* __restrict__ cur,
                                int* __restrict__ pay) {
    int e = blockIdx.x * blockDim.x + threadIdx.x;
    if (e < E) {
        int d = dst[e];
        int pos = offs[d] + atomicAdd(&cur[d], 1);
        pay[pos] = src[e] | (type << 28);
    }
}

// ------------------------- aggregation kernels -------------------------
__global__ void aggL2C_kernel(const int* __restrict__ pay, const int* __restrict__ offs,
                              const fp16* __restrict__ G, const float* __restrict__ beff,
                              fp16* __restrict__ MSG, int ndst) {
    int w = (blockIdx.x * blockDim.x + threadIdx.x) >> 5;
    int lane = threadIdx.x & 31;
    if (w >= ndst) return;
    int beg = offs[w], end = offs[w + 1];
    float a0 = 0.f, a1 = 0.f, a2 = 0.f, a3 = 0.f;
    int d0 = 0, d1 = 0, d2 = 0;
    int j = lane * 4;
    for (int i = beg; i < end; i++) {
        unsigned p = (unsigned)__ldg(pay + i);
        int s = (int)(p & 0x0FFFFFFFu);
        int t = (int)(p >> 28);
        const fp162* src = (const fp162*)(G + (size_t)s * 384 + t * 128 + j);
        float2 f0 = __half22float2(src[0]);
        float2 f1 = __half22float2(src[1]);
        a0 += f0.x; a1 += f0.y; a2 += f1.x; a3 += f1.y;
        d0 += (t == 0); d1 += (t == 1); d2 += (t == 2);
    }
    float fd0 = (float)d0, fd1 = (float)d1, fd2 = (float)d2;
    a0 += fd0 * beff[j + 0] + fd1 * beff[128 + j + 0] + fd2 * beff[256 + j + 0];
    a1 += fd0 * beff[j + 1] + fd1 * beff[128 + j + 1] + fd2 * beff[256 + j + 1];
    a2 += fd0 * beff[j + 2] + fd1 * beff[128 + j + 2] + fd2 * beff[256 + j + 2];
    a3 += fd0 * beff[j + 3] + fd1 * beff[128 + j + 3] + fd2 * beff[256 + j + 3];
    fp162* dst = (fp162*)(MSG + (size_t)w * 128 + j);
    dst[0] = __floats2half2_rn(a0, a1);
    dst[1] = __floats2half2_rn(a2, a3);
}

__global__ void aggC2L_kernel(const int* __restrict__ pay, const int* __restrict__ offs,
                              const fp16* __restrict__ H, fp16* __restrict__ AGG, int ndst) {
    int w = (blockIdx.x * blockDim.x + threadIdx.x) >> 5;
    int lane = threadIdx.x & 31;
    if (w >= ndst) return;
    int beg = offs[w], end = offs[w + 1];
    float a[3][4];
#pragma unroll
    for (int t = 0; t < 3; t++)
#pragma unroll
        for (int q = 0; q < 4; q++) a[t][q] = 0.f;
    int d0 = 0, d1 = 0, d2 = 0;
    int j = lane * 4;
    for (int i = beg; i < end; i++) {
        unsigned p = (unsigned)__ldg(pay + i);
        int s = (int)(p & 0x0FFFFFFFu);
        int t = (int)(p >> 28);
        const fp162* src = (const fp162*)(H + (size_t)s * 128 + j);
        float2 f0 = __half22float2(src[0]);
        float2 f1 = __half22float2(src[1]);
        if (t == 0)      { a[0][0] += f0.x; a[0][1] += f0.y; a[0][2] += f1.x; a[0][3] += f1.y; d0++; }
        else if (t == 1) { a[1][0] += f0.x; a[1][1] += f0.y; a[1][2] += f1.x; a[1][3] += f1.y; d1++; }
        else             { a[2][0] += f0.x; a[2][1] += f0.y; a[2][2] += f1.x; a[2][3] += f1.y; d2++; }
    }
    size_t base = (size_t)w * KAGG;
#pragma unroll
    for (int t = 0; t < 3; t++) {
        fp162* dst = (fp162*)(AGG + base + t * 128 + j);
        dst[0] = __floats2half2_rn(a[t][0], a[t][1]);
        dst[1] = __floats2half2_rn(a[t][2], a[t][3]);
    }
    if (lane < 8) {
        fp162* dst = (fp162*)(AGG + base + 384 + lane * 4);
        fp162 z = __floats2half2_rn(0.f, 0.f);
        dst[0] = z; dst[1] = z;
    }
    __syncwarp();
    if (lane == 0) {
        AGG[base + 384] = __float2half_rn((float)d0);
        AGG[base + 385] = __float2half_rn((float)d1);
        AGG[base + 386] = __float2half_rn((float)d2);
    }
}

// ------------------------- cp.async helpers -------------------------
__device__ __forceinline__ void cp16(uint32_t dst, const void* src, int sz) {
    asm volatile("cp.async.cg.shared.global [%0], [%1], 16, %2;" :: "r"(dst), "l"(src), "r"(sz));
}
__device__ __forceinline__ void cp_commit() { asm volatile("cp.async.commit_group;"); }
__device__ __forceinline__ void cp_wait0() { asm volatile("cp.async.wait_group 0;"); }
__device__ __forceinline__ void cp_wait1() { asm volatile("cp.async.wait_group 1;"); }

__device__ __forceinline__ void ldm_x4(uint32_t addr, uint32_t& r0, uint32_t& r1, uint32_t& r2, uint32_t& r3) {
    asm volatile("ldmatrix.sync.aligned.m8n8.x4.shared.b16 {%0,%1,%2,%3}, [%4];"
                 : "=r"(r0), "=r"(r1), "=r"(r2), "=r"(r3) : "r"(addr));
}

#define MMA16(d, a, b)                                                                             \
    asm volatile("mma.sync.aligned.m16n8k16.row.col.f32.f16.f16.f32 "                             \
                 "{%0,%1,%2,%3},{%4,%5,%6,%7},{%8,%9},{%0,%1,%2,%3};"                             \
                 : "+f"(d[0]), "+f"(d[1]), "+f"(d[2]), "+f"(d[3])                                  \
                 : "r"(a[0]), "r"(a[1]), "r"(a[2]), "r"(a[3]), "r"(b[0]), "r"(b[1]))

// smem geometry (halves)
#define MM_STR 40
#define MM_STAGE_HALVES (128 * MM_STR)
#define MM_SMEM_HALVES  (3 * 2 * MM_STAGE_HALVES)
#define MM_SMEM_BYTES   (MM_SMEM_HALVES * 2)             // 61440

// ------------------------- unified fp16 tensor-core GEMM -------------------------
// 256 threads, 8 warps, warp tile 32x64 (round-6 champion geometry).
// Y[M,N] = X[M,K] @ W[N,K]^T (+ bias)
// XMODE: 0 plain (stride=K), 1 [MSG|Ch], 2 [MSG|flip|H], 3 [L[:NV]|L[NV:]]
// EPI:   0 bias-store, 1 bias-relu-store, 2 fused LSTM cell (gate-permuted weights, fp16 c)
// GSWAP: 1 -> (m,n)=(by,bx): n-blocks schedule-adjacent for L2 X reuse
// 3-stage cp.async ring, ONE __syncthreads per K-iter.
template <int XMODE, int EPI, int K, int GSWAP>
__global__ void __launch_bounds__(256, 2) mm_kernel(
    const fp16* __restrict__ X0, const fp16* __restrict__ X1,
    const fp16* __restrict__ W, const float* __restrict__ bias,
    fp16* __restrict__ Y, int ldY,
    const fp16* __restrict__ Cold, fp16* __restrict__ Hnew, fp16* __restrict__ Cnew,
    int M) {
    extern __shared__ __align__(16) fp16 smraw[];
    fp16* xs = smraw;                          // [3][128][MM_STR]
    fp16* ws = smraw + 3 * MM_STAGE_HALVES;    // [3][128][MM_STR]
    const int tid = threadIdx.x;
    const int lane = tid & 31, warp = tid >> 5;
    const int wm = warp & 3, wn = warp >> 2;
    const int mblk = GSWAP ? blockIdx.y : blockIdx.x;
    const int nblk = GSWAP ? blockIdx.x : blockIdx.y;
    const int row0 = mblk * 128, n0 = nblk * 128;
    const uint32_t xs_u = (uint32_t)__cvta_generic_to_shared(xs);
    const uint32_t ws_u = (uint32_t)__cvta_generic_to_shared(ws);

    float acc[2][8][4];
#pragma unroll
    for (int a = 0; a < 2; a++)
#pragma unroll
        for (int b = 0; b < 8; b++)
#pragma unroll
            for (int c = 0; c < 4; c++) acc[a][b][c] = 0.0f;

    auto load_tiles = [&](int it, int buf) {
        int kb = it * 32;
        uint32_t xbase = xs_u + (uint32_t)(buf * MM_STAGE_HALVES * 2);
        uint32_t wbase = ws_u + (uint32_t)(buf * MM_STAGE_HALVES * 2);
#pragma unroll
        for (int q = 0; q < 2; q++) {
            int chunk = tid + 256 * q;
            int r = chunk >> 2, cc = chunk & 3;
            int gr = row0 + r;
            int grc = gr < M ? gr : (M - 1);
            int gk = kb + cc * 8;
            const fp16* src;
            if (XMODE == 0) {
                src = X0 + (size_t)grc * K + gk;
            } else if (XMODE == 1) {
                src = (gk < 128) ? X0 + (size_t)grc * 128 + gk
                                 : X1 + (size_t)grc * 128 + (gk - 128);
            } else if (XMODE == 2) {
                if (gk < 128) src = X0 + (size_t)grc * 128 + gk;
                else if (gk < 256) {
                    int fr = (grc < NV) ? grc + NV : grc - NV;
                    src = X1 + (size_t)fr * 128 + (gk - 128);
                } else src = X1 + (size_t)grc * 128 + (gk - 256);
            } else {  // XMODE 3
                src = (gk < 128) ? X0 + (size_t)grc * 128 + gk
                                 : X0 + (size_t)(grc + NV) * 128 + (gk - 128);
            }
            cp16(xbase + (uint32_t)((r * MM_STR + cc * 8) * 2), src, gr < M ? 16 : 0);
        }
#pragma unroll
        for (int q = 0; q < 2; q++) {
            int chunk = tid + 256 * q;
            int n = chunk >> 2, cc = chunk & 3;
            const fp16* src = W + (size_t)(n0 + n) * K + kb + cc * 8;
            cp16(wbase + (uint32_t)((n * MM_STR + cc * 8) * 2), src, 16);
        }
        cp_commit();
    };

    auto compute = [&](int buf) {
        uint32_t xbase = xs_u + (uint32_t)(buf * MM_STAGE_HALVES * 2);
        uint32_t wbase = ws_u + (uint32_t)(buf * MM_STAGE_HALVES * 2);
#pragma unroll
        for (int ks = 0; ks < 2; ks++) {
            int coloff = ks * 16 + ((lane >> 4) & 1) * 8;
            uint32_t afrag[2][4];
#pragma unroll
            for (int mt = 0; mt < 2; mt++) {
                int r = wm * 32 + mt * 16 + (lane & 15);
                uint32_t addr = xbase + (uint32_t)((r * MM_STR + coloff) * 2);
                ldm_x4(addr, afrag[mt][0], afrag[mt][1], afrag[mt][2], afrag[mt][3]);
            }
            uint32_t bfrag[8][2];
#pragma unroll
            for (int p = 0; p < 4; p++) {
                int n = wn * 64 + p * 16 + (lane & 15);
                uint32_t addr = wbase + (uint32_t)((n * MM_STR + coloff) * 2);
                uint32_t r0, r1, r2, r3;
                ldm_x4(addr, r0, r1, r2, r3);
                bfrag[2 * p][0] = r0; bfrag[2 * p][1] = r2;
                bfrag[2 * p + 1][0] = r1; bfrag[2 * p + 1][1] = r3;
            }
#pragma unroll
            for (int mt = 0; mt < 2; mt++)
#pragma unroll
                for (int nt = 0; nt < 8; nt++) MMA16(acc[mt][nt], afrag[mt], bfrag[nt]);
        }
    };

    constexpr int ITERS = K / 32;
    load_tiles(0, 0);
    load_tiles(1, 1);
    for (int it = 0; it < ITERS; it++) {
        if (it + 1 < ITERS) cp_wait1(); else cp_wait0();
        __syncthreads();
        if (it + 2 < ITERS) load_tiles(it + 2, (it + 2) % 3);
        compute(it % 3);
    }
    __syncthreads();   // protect epilogue smem reuse from lagging warps

    if (EPI == 0 || EPI == 1) {
#pragma unroll
        for (int mt = 0; mt < 2; mt++) {
#pragma unroll
            for (int nt = 0; nt < 8; nt++) {
                int gr0 = row0 + wm * 32 + mt * 16 + (lane >> 2);
                int col = n0 + wn * 64 + nt * 8 + 2 * (lane & 3);
                float b0v = __ldg(bias + col), b1v = __ldg(bias + col + 1);
                float v0 = acc[mt][nt][0] + b0v, v1 = acc[mt][nt][1] + b1v;
                float v2 = acc[mt][nt][2] + b0v, v3 = acc[mt][nt][3] + b1v;
                if (EPI == 1) {
                    v0 = fmaxf(v0, 0.f); v1 = fmaxf(v1, 0.f);
                    v2 = fmaxf(v2, 0.f); v3 = fmaxf(v3, 0.f);
                }
                if (gr0 < M)
                    *(fp162*)(Y + (size_t)gr0 * ldY + col) = __floats2half2_rn(v0, v1);
                if (gr0 + 8 < M)
                    *(fp162*)(Y + (size_t)(gr0 + 8) * ldY + col) = __floats2half2_rn(v2, v3);
            }
        }
    } else {
        // fused LSTM epilogue; this block handles kk in [nblk*32, +32); fp16 cell state
        const int kk0 = nblk * 32;
        float* cs = (float*)smraw;        // [128][33]
        float* hs = cs + 128 * 33;        // [128][33]
        for (int i = tid; i < 1024; i += 256) {
            int r = i >> 3, c = (i & 7) * 4;
            int gr = row0 + r;
            if (gr < M) {
                const fp162* cp = (const fp162*)(Cold + (size_t)gr * 128 + kk0 + c);
                float2 va = __half22float2(cp[0]);
                float2 vb = __half22float2(cp[1]);
                cs[r * 33 + c + 0] = va.x; cs[r * 33 + c + 1] = va.y;
                cs[r * 33 + c + 2] = vb.x; cs[r * 33 + c + 3] = vb.y;
            }
        }
        __syncthreads();
        const int odd = lane & 1;
#pragma unroll
        for (int nt = 0; nt < 8; nt++) {
            int colp = wn * 64 + nt * 8 + 2 * (lane & 3);
            float b0v = __ldg(bias + n0 + colp), b1v = __ldg(bias + n0 + colp + 1);
            int kkl = colp >> 2;
#pragma unroll
            for (int mt = 0; mt < 2; mt++) {
                float c0 = acc[mt][nt][0] + b0v, c1 = acc[mt][nt][1] + b1v;
                float c2 = acc[mt][nt][2] + b0v, c3 = acc[mt][nt][3] + b1v;
                float x0 = __shfl_xor_sync(0xffffffffu, c0, 1);
                float x1 = __shfl_xor_sync(0xffffffffu, c1, 1);
                float x2 = __shfl_xor_sync(0xffffffffu, c2, 1);
                float x3 = __shfl_xor_sync(0xffffffffu, c3, 1);
                float gi = odd ? x2 : c0;
                float gf = odd ? x3 : c1;
                float gg = odd ? c2 : x0;
                float go = odd ? c3 : x1;
                int rloc = wm * 32 + mt * 16 + (lane >> 2) + odd * 8;
                float cold = cs[rloc * 33 + kkl];
                float c2v = sigmoidf_(gf) * cold + sigmoidf_(gi) * tanhf(gg);
                float h = sigmoidf_(go) * tanhf(c2v);
                cs[rloc * 33 + kkl] = c2v;
                hs[rloc * 33 + kkl] = h;
            }
        }
        __syncthreads();
        for (int i = tid; i < 1024; i += 256) {
            int r = i >> 3, c = (i & 7) * 4;
            int gr = row0 + r;
            if (gr < M) {
                fp162* cd = (fp162*)(Cnew + (size_t)gr * 128 + kk0 + c);
                cd[0] = __floats2half2_rn(cs[r * 33 + c], cs[r * 33 + c + 1]);
                cd[1] = __floats2half2_rn(cs[r * 33 + c + 2], cs[r * 33 + c + 3]);
                fp162* hp = (fp162*)(Hnew + (size_t)gr * 128 + kk0 + c);
                hp[0] = __floats2half2_rn(hs[r * 33 + c], hs[r * 33 + c + 1]);
                hp[1] = __floats2half2_rn(hs[r * 33 + c + 2], hs[r * 33 + c + 3]);
            }
        }
    }
}

// ------------------------- final vote -------------------------
__global__ void vote_kernel(const fp16* __restrict__ H2, const float* __restrict__ w3,
                            const float* __restrict__ b3, float* __restrict__ out, int M) {
    int w = (blockIdx.x * blockDim.x + threadIdx.x) >> 5;
    int lane = threadIdx.x & 31;
    if (w < M) {
        float s = 0.0f;
#pragma unroll
        for (int q = 0; q < 4; q++) {
            int j = lane + 32 * q;
            s += __half2float(H2[(size_t)w * 128 + j]) * __ldg(w3 + j);
        }
#pragma unroll
        for (int o = 16; o > 0; o >>= 1) s += __shfl_xor_sync(0xffffffffu, s, o);
        if (lane == 0) out[w] = s + b3[0];
    }
}

// ------------------------- host orchestration -------------------------
static void build_csr(const int* src0, const int* dst0, int E0,
                      const int* src1, const int* dst1, int E1,
                      const int* src2, const int* dst2, int E2,
                      int ndst, int* offs, int* pay,
                      int* cnt, int* cur, int* exsc, int* blksum) {
    zero_int_kernel<<<(ndst + 255) / 256, 256>>>(cnt, ndst);
    hist_kernel<<<(E0 + 255) / 256, 256>>>(dst0, E0, cnt);
    hist_kernel<<<(E1 + 255) / 256, 256>>>(dst1, E1, cnt);
    hist_kernel<<<(E2 + 255) / 256, 256>>>(dst2, E2, cnt);
    int nb = (ndst + 1023) / 1024;
    scanA_kernel<<<nb, 1024>>>(cnt, exsc, blksum, ndst);
    scanB_kernel<<<1, 32>>>(blksum, nb);
    scanC_kernel<<<(ndst + 255) / 256, 256>>>(exsc, blksum, offs, ndst, E0 + E1 + E2);
    zero_int_kernel<<<(ndst + 255) / 256, 256>>>(cur, ndst);
    fill_csr_kernel<<<(E0 + 255) / 256, 256>>>(src0, dst0, E0, 0, offs, cur, pay);
    fill_csr_kernel<<<(E1 + 255) / 256, 256>>>(src1, dst1, E1, 1, offs, cur, pay);
    fill_csr_kernel<<<(E2 + 255) / 256, 256>>>(src2, dst2, E2, 2, offs, cur, pay);
}

extern "C" void kernel_launch(void* const* d_in, const int* in_sizes, int n_in,
                              void* d_out, int out_size) {
    (void)in_sizes; (void)n_in; (void)out_size;
    const float* l_init_w   = (const float*)d_in[0];
    const float* l_init_b   = (const float*)d_in[1];
    const float* c_init_w   = (const float*)d_in[2];
    const float* c_init_b   = (const float*)d_in[3];
    const float* mha_in_w   = (const float*)d_in[4];
    const float* mha_in_b   = (const float*)d_in[5];
    const float* mha_out_w  = (const float*)d_in[6];
    const float* mha_out_b  = (const float*)d_in[7];
    const float* lstm_L_wih = (const float*)d_in[8];
    const float* lstm_L_whh = (const float*)d_in[9];
    const float* lstm_L_bih = (const float*)d_in[10];
    const float* lstm_L_bhh = (const float*)d_in[11];
    const float* lstm_C_wih = (const float*)d_in[12];
    const float* lstm_C_whh = (const float*)d_in[13];
    const float* lstm_C_bih = (const float*)d_in[14];
    const float* lstm_C_bhh = (const float*)d_in[15];
    const float* mlp_w1     = (const float*)d_in[16];
    const float* mlp_b1     = (const float*)d_in[17];
    const float* mlp_w2     = (const float*)d_in[18];
    const float* mlp_b2     = (const float*)d_in[19];
    const float* mlp_w3     = (const float*)d_in[20];
    const float* mlp_b3     = (const float*)d_in[21];
    const int* child_lit    = (const int*)d_in[22];
    const int* child_clause = (const int*)d_in[23];
    const int* fa_lit       = (const int*)d_in[24];
    const int* fa_clause    = (const int*)d_in[25];
    const int* nt_lit       = (const int*)d_in[26];
    const int* nt_clause    = (const int*)d_in[27];

    fp16 *Lh0, *Lh1, *Lc, *Ch0, *Ch1, *Cc, *MSG, *G, *AGG, *WgatC, *WcatL, *WC, *WL, *W1, *W2;
    float *Weff, *beff, *bC, *bL, *zeroB;
    int *offsLC, *offsCL, *payLC, *payCL, *cnt, *cur, *exsc, *blksum;
    cudaGetSymbolAddress((void**)&Lh0, g_Lh0);
    cudaGetSymbolAddress((void**)&Lh1, g_Lh1);
    cudaGetSymbolAddress((void**)&Lc,  g_Lc);
    cudaGetSymbolAddress((void**)&Ch0, g_Ch0);
    cudaGetSymbolAddress((void**)&Ch1, g_Ch1);
    cudaGetSymbolAddress((void**)&Cc,  g_Cc);
    cudaGetSymbolAddress((void**)&MSG, g_MSG);
    cudaGetSymbolAddress((void**)&G,   g_G);
    cudaGetSymbolAddress((void**)&AGG, g_AGG);
    cudaGetSymbolAddress((void**)&Weff, g_Weff);
    cudaGetSymbolAddress((void**)&beff, g_beff);
    cudaGetSymbolAddress((void**)&WgatC, g_WgatC);
    cudaGetSymbolAddress((void**)&WcatL, g_WcatL);
    cudaGetSymbolAddress((void**)&WC, g_WC);
    cudaGetSymbolAddress((void**)&bC, g_bC);
    cudaGetSymbolAddress((void**)&WL, g_WL);
    cudaGetSymbolAddress((void**)&bL, g_bL);
    cudaGetSymbolAddress((void**)&W1, g_W1);
    cudaGetSymbolAddress((void**)&W2, g_W2);
    cudaGetSymbolAddress((void**)&zeroB, g_zero);
    cudaGetSymbolAddress((void**)&offsLC, g_offsLC);
    cudaGetSymbolAddress((void**)&offsCL, g_offsCL);
    cudaGetSymbolAddress((void**)&payLC, g_payLC);
    cudaGetSymbolAddress((void**)&payCL, g_payCL);
    cudaGetSymbolAddress((void**)&cnt, g_cnt);
    cudaGetSymbolAddress((void**)&cur, g_cur);
    cudaGetSymbolAddress((void**)&exsc, g_exsc);
    cudaGetSymbolAddress((void**)&blksum, g_blksum);

    cudaFuncSetAttribute(mm_kernel<0, 0, 128, 1>, cudaFuncAttributeMaxDynamicSharedMemorySize, MM_SMEM_BYTES);
    cudaFuncSetAttribute(mm_kernel<1, 2, 256, 1>, cudaFuncAttributeMaxDynamicSharedMemorySize, MM_SMEM_BYTES);
    cudaFuncSetAttribute(mm_kernel<0, 0, KAGG, 0>, cudaFuncAttributeMaxDynamicSharedMemorySize, MM_SMEM_BYTES);
    cudaFuncSetAttribute(mm_kernel<2, 2, 384, 1>, cudaFuncAttributeMaxDynamicSharedMemorySize, MM_SMEM_BYTES);
    cudaFuncSetAttribute(mm_kernel<3, 1, 256, 0>, cudaFuncAttributeMaxDynamicSharedMemorySize, MM_SMEM_BYTES);
    cudaFuncSetAttribute(mm_kernel<0, 1, 128, 0>, cudaFuncAttributeMaxDynamicSharedMemorySize, MM_SMEM_BYTES);

    // ---- setup ----
    compute_weff_kernel<<<dim3(128, 6), 128>>>(mha_in_w, mha_in_b, mha_out_w, mha_out_b, Weff, beff);
    prep_wgat_kernel<<<384, 128>>>(Weff, WgatC);
    prep_wcatL_kernel<<<128, KAGG>>>(Weff, beff, WcatL);
    prep_lstm_kernel<<<512, 256>>>(lstm_C_wih, lstm_C_whh, lstm_C_bih, lstm_C_bhh, WC, bC, 128);
    prep_lstm_kernel<<<512, 384>>>(lstm_L_wih, lstm_L_whh, lstm_L_bih, lstm_L_bhh, WL, bL, 256);
    prep_mlp_kernel<<<(128 * 256 + 255) / 256, 256>>>(mlp_w1, mlp_w2, W1, W2);
    init_state_kernel<<<(int)(((size_t)NC * DIM + 255) / 256), 256>>>(
        l_init_w, l_init_b, c_init_w, c_init_b, Lh0, Lc, Ch0, Cc);

    build_csr(child_lit, child_clause, ECNT, fa_lit, fa_clause, EFNT, nt_lit, nt_clause, ENNT,
              NC, offsLC, payLC, cnt, cur, exsc, blksum);
    build_csr(child_clause, child_lit, ECNT, fa_clause, fa_lit, EFNT, nt_clause, nt_lit, ENNT,
              NL, offsCL, payCL, cnt, cur, exsc, blksum);

    fp16* Lcur = Lh0; fp16* Lnxt = Lh1;
    fp16* Ccur = Ch0; fp16* Cnxt = Ch1;

    const int GB_L = (NL + 127) / 128;   // 782
    const int GB_C = (NC + 127) / 128;   // 1641
    const int GB_V = (NV + 127) / 128;   // 391

    for (int r = 0; r < ROUNDS; r++) {
        // ---- L -> C: transform L (small side), gather-aggregate into MSG ----
        mm_kernel<0, 0, 128, 1><<<dim3(3, GB_L), 256, MM_SMEM_BYTES>>>(
            Lcur, nullptr, WgatC, zeroB, G, 384, nullptr, nullptr, nullptr, NL);
        aggL2C_kernel<<<(NC * 32 + 255) / 256, 256>>>(payLC, offsLC, G, beff, MSG, NC);
        mm_kernel<1, 2, 256, 1><<<dim3(4, GB_C), 256, MM_SMEM_BYTES>>>(
            MSG, Ccur, WC, bC, nullptr, 0, Cc, Cnxt, Cc, NC);
        { fp16* t = Ccur; Ccur = Cnxt; Cnxt = t; }

        // ---- C -> L: aggregate C (small dst side), then transform ----
        aggC2L_kernel<<<(NL * 32 + 255) / 256, 256>>>(payCL, offsCL, Ccur, AGG, NL);
        mm_kernel<0, 0, KAGG, 0><<<dim3(GB_L, 1), 256, MM_SMEM_BYTES>>>(
            AGG, nullptr, WcatL, zeroB, MSG, 128, nullptr, nullptr, nullptr, NL);
        mm_kernel<2, 2, 384, 1><<<dim3(4, GB_L), 256, MM_SMEM_BYTES>>>(
            MSG, Lcur, WL, bL, nullptr, 0, Lc, Lnxt, Lc, NL);
        { fp16* t = Lcur; Lcur = Lnxt; Lnxt = t; }
    }

    // ---- final MLP ----
    mm_kernel<3, 1, 256, 0><<<dim3(GB_V, 1), 256, MM_SMEM_BYTES>>>(
        Lcur, nullptr, W1, mlp_b1, G, 128, nullptr, nullptr, nullptr, NV);
    mm_kernel<0, 1, 128, 0><<<dim3(GB_V, 1), 256, MM_SMEM_BYTES>>>(
        G, nullptr, W2, mlp_b2, MSG, 128, nullptr, nullptr, nullptr, NV);
    vote_kernel<<<(NV * 32 + 255) / 256, 256>>>(MSG, mlp_w3, mlp_b3, (float*)d_out, NV);
}

// round 10
// speedup vs baseline: 1.5010x; 1.1793x over previous
#include <cuda_runtime.h>
#include <cuda_fp16.h>
#include <math.h>
#include <stdint.h>

#define DIM 128
#define NV 50000
#define NL 100000
#define NC 210000
#define ECNT 300000
#define EFNT 100000
#define ENNT 200000
#define ETOT 600000
#define ROUNDS 8
#define KAGG 416   // 384 sums + 3 deg + 29 zero pad (multiple of 32)

typedef __half fp16;
typedef __half2 fp162;

// ------------------------- static device scratch -------------------------
__device__ fp16  g_Lh0[(size_t)NL * DIM];
__device__ fp16  g_Lh1[(size_t)NL * DIM];
__device__ fp16  g_Lc [(size_t)NL * DIM];
__device__ fp16  g_Ch0[(size_t)NC * DIM];
__device__ fp16  g_Ch1[(size_t)NC * DIM];
__device__ fp16  g_Cc [(size_t)NC * DIM];
__device__ fp16  g_MSG[(size_t)NC * DIM];
__device__ fp16  g_G  [(size_t)NL * 384];
__device__ fp16  g_AGG[(size_t)NL * KAGG];
__device__ float g_Weff[6 * DIM * DIM];
__device__ float g_beff[6 * DIM];
__device__ fp16  g_WgatC[384 * DIM];
__device__ fp16  g_WcatL[DIM * KAGG];
__device__ fp16  g_WC[512 * 256];
__device__ float g_bC[512];
__device__ fp16  g_WL[512 * 384];
__device__ float g_bL[512];
__device__ fp16  g_W1[128 * 256];
__device__ fp16  g_W2[128 * 128];
__device__ float g_zero[512];
// CSR scratch
__device__ int g_offsLC[NC + 1];
__device__ int g_offsCL[NL + 1];
__device__ int g_payLC[ETOT];
__device__ int g_payCL[ETOT];
__device__ int g_cnt[NC];
__device__ int g_cur[NC];
__device__ int g_exsc[NC];
__device__ int g_blksum[256];

__device__ __forceinline__ float sigmoidf_(float x) { return 1.0f / (1.0f + __expf(-x)); }

// fast transcendental path for LSTM epilogue (MUFU.TANH, sm_75+)
__device__ __forceinline__ float tanh_fast(float x) {
    float y;
    asm("tanh.approx.f32 %0, %1;" : "=f"(y) : "f"(x));
    return y;
}
__device__ __forceinline__ float sigmoid_fast(float x) {
    return fmaf(tanh_fast(0.5f * x), 0.5f, 0.5f);
}

// ------------------------- weff precompute (fp32) -------------------------
__global__ void compute_weff_kernel(const float* __restrict__ mha_in_w,
                                    const float* __restrict__ mha_in_b,
                                    const float* __restrict__ mha_out_w,
                                    const float* __restrict__ mha_out_b,
                                    float* __restrict__ Weff,
                                    float* __restrict__ beff) {
    int o = blockIdx.x, t = blockIdx.y, v = threadIdx.x;
    const float* Wo = mha_out_w + (size_t)t * DIM * DIM + (size_t)o * DIM;
    const float* Wv = mha_in_w + (size_t)t * 3 * DIM * DIM + (size_t)2 * DIM * DIM;
    float acc = 0.0f;
#pragma unroll 8
    for (int j = 0; j < DIM; j++) acc += Wo[j] * Wv[(size_t)j * DIM + v];
    Weff[((size_t)t * DIM + o) * DIM + v] = acc;
    if (v == 0) {
        const float* bv = mha_in_b + t * 3 * DIM + 2 * DIM;
        float s = 0.0f;
        for (int j = 0; j < DIM; j++) s += Wo[j] * bv[j];
        beff[t * DIM + o] = s + mha_out_b[t * DIM + o];
    }
}

__global__ void prep_wgat_kernel(const float* __restrict__ Weff, fp16* __restrict__ Wg) {
    int n = blockIdx.x, k = threadIdx.x;
    Wg[(size_t)n * 128 + k] = __float2half_rn(Weff[(size_t)n * 128 + k]);
}

__global__ void prep_wcatL_kernel(const float* __restrict__ Weff, const float* __restrict__ beff,
                                  fp16* __restrict__ Wc) {
    int n = blockIdx.x, k = threadIdx.x;   // 0..415
    float v;
    if (k < 384) {
        int t = k >> 7, j = k & 127;
        v = Weff[(((size_t)(3 + t)) * DIM + n) * DIM + j];
    } else if (k < 387) {
        v = beff[(3 + (k - 384)) * DIM + n];
    } else v = 0.0f;
    Wc[(size_t)n * KAGG + k] = __float2half_rn(v);
}

__global__ void prep_lstm_kernel(const float* __restrict__ wih, const float* __restrict__ whh,
                                 const float* __restrict__ bih, const float* __restrict__ bhh,
                                 fp16* __restrict__ Wd, float* __restrict__ bd, int KX) {
    int n = blockIdx.x, k = threadIdx.x;
    int K = KX + 128;
    int orig = (n & 3) * 128 + (n >> 2);
    float v = (k < KX) ? wih[(size_t)orig * KX + k] : whh[(size_t)orig * 128 + (k - KX)];
    Wd[(size_t)n * K + k] = __float2half_rn(v);
    if (k == 0) bd[n] = bih[orig] + bhh[orig];
}

__global__ void prep_mlp_kernel(const float* __restrict__ w1, const float* __restrict__ w2,
                                fp16* __restrict__ W1r, fp16* __restrict__ W2r) {
    int i = blockIdx.x * blockDim.x + threadIdx.x;
    if (i < 128 * 256) W1r[i] = __float2half_rn(w1[i]);
    if (i < 128 * 128) W2r[i] = __float2half_rn(w2[i]);
}

__global__ void init_state_kernel(const float* __restrict__ lw, const float* __restrict__ lb,
                                  const float* __restrict__ cw, const float* __restrict__ cb,
                                  fp16* __restrict__ Lh, fp16* __restrict__ Lc,
                                  fp16* __restrict__ Ch, fp16* __restrict__ Cc) {
    size_t idx = (size_t)blockIdx.x * blockDim.x + threadIdx.x;
    int j = (int)(idx & (DIM - 1));
    fp16 z = __float2half_rn(0.0f);
    if (idx < (size_t)NL * DIM) { Lh[idx] = __float2half_rn(lw[j] + lb[j]); Lc[idx] = z; }
    if (idx < (size_t)NC * DIM) { Ch[idx] = __float2half_rn(cw[j] + cb[j]); Cc[idx] = z; }
}

// ------------------------- CSR build -------------------------
__global__ void zero_int_kernel(int* __restrict__ p, int n) {
    int i = blockIdx.x * blockDim.x + threadIdx.x;
    if (i < n) p[i] = 0;
}
__global__ void hist_kernel(const int* __restrict__ dst, int E, int* __restrict__ cnt) {
    int e = blockIdx.x * blockDim.x + threadIdx.x;
    if (e < E) atomicAdd(&cnt[dst[e]], 1);
}
__global__ void scanA_kernel(const int* __restrict__ cnt, int* __restrict__ exsc,
                             int* __restrict__ blksum, int n) {
    __shared__ int sm[1024];
    int tid = threadIdx.x;
    int i = blockIdx.x * 1024 + tid;
    int v = (i < n) ? cnt[i] : 0;
    sm[tid] = v;
    __syncthreads();
    for (int o = 1; o < 1024; o <<= 1) {
        int t = (tid >= o) ? sm[tid - o] : 0;
        __syncthreads();
        sm[tid] += t;
        __syncthreads();
    }
    if (i < n) exsc[i] = sm[tid] - v;
    if (tid == 1023) blksum[blockIdx.x] = sm[1023];
}
__global__ void scanB_kernel(int* __restrict__ blksum, int nb) {
    if (threadIdx.x == 0 && blockIdx.x == 0) {
        int s = 0;
        for (int b = 0; b < nb; b++) { int t = blksum[b]; blksum[b] = s; s += t; }
    }
}
__global__ void scanC_kernel(const int* __restrict__ exsc, const int* __restrict__ blksum,
                             int* __restrict__ offs, int n, int E) {
    int i = blockIdx.x * blockDim.x + threadIdx.x;
    if (i < n) offs[i] = exsc[i] + blksum[i >> 10];
    if (i == 0) offs[n] = E;
}
__global__ void fill_csr_kernel(const int* __restrict__ src, const int* __restrict__ dst, int E,
                                int type, const int* __restrict__ offs, int* __restrict__ cur,
                                int* __restrict__ pay) {
    int e = blockIdx.x * blockDim.x + threadIdx.x;
    if (e < E) {
        int d = dst[e];
        int pos = offs[d] + atomicAdd(&cur[d], 1);
        pay[pos] = src[e] | (type << 28);
    }
}

// ------------------------- aggregation kernels -------------------------
__global__ void aggL2C_kernel(const int* __restrict__ pay, const int* __restrict__ offs,
                              const fp16* __restrict__ G, const float* __restrict__ beff,
                              fp16* __restrict__ MSG, int ndst) {
    int w = (blockIdx.x * blockDim.x + threadIdx.x) >> 5;
    int lane = threadIdx.x & 31;
    if (w >= ndst) return;
    int beg = offs[w], end = offs[w + 1];
    float a0 = 0.f, a1 = 0.f, a2 = 0.f, a3 = 0.f;
    int d0 = 0, d1 = 0, d2 = 0;
    int j = lane * 4;
    for (int i = beg; i < end; i++) {
        unsigned p = (unsigned)__ldg(pay + i);
        int s = (int)(p & 0x0FFFFFFFu);
        int t = (int)(p >> 28);
        const fp162* src = (const fp162*)(G + (size_t)s * 384 + t * 128 + j);
        float2 f0 = __half22float2(src[0]);
        float2 f1 = __half22float2(src[1]);
        a0 += f0.x; a1 += f0.y; a2 += f1.x; a3 += f1.y;
        d0 += (t == 0); d1 += (t == 1); d2 += (t == 2);
    }
    float fd0 = (float)d0, fd1 = (float)d1, fd2 = (float)d2;
    a0 += fd0 * beff[j + 0] + fd1 * beff[128 + j + 0] + fd2 * beff[256 + j + 0];
    a1 += fd0 * beff[j + 1] + fd1 * beff[128 + j + 1] + fd2 * beff[256 + j + 1];
    a2 += fd0 * beff[j + 2] + fd1 * beff[128 + j + 2] + fd2 * beff[256 + j + 2];
    a3 += fd0 * beff[j + 3] + fd1 * beff[128 + j + 3] + fd2 * beff[256 + j + 3];
    fp162* dst = (fp162*)(MSG + (size_t)w * 128 + j);
    dst[0] = __floats2half2_rn(a0, a1);
    dst[1] = __floats2half2_rn(a2, a3);
}

__global__ void aggC2L_kernel(const int* __restrict__ pay, const int* __restrict__ offs,
                              const fp16* __restrict__ H, fp16* __restrict__ AGG, int ndst) {
    int w = (blockIdx.x * blockDim.x + threadIdx.x) >> 5;
    int lane = threadIdx.x & 31;
    if (w >= ndst) return;
    int beg = offs[w], end = offs[w + 1];
    float a[3][4];
#pragma unroll
    for (int t = 0; t < 3; t++)
#pragma unroll
        for (int q = 0; q < 4; q++) a[t][q] = 0.f;
    int d0 = 0, d1 = 0, d2 = 0;
    int j = lane * 4;
    for (int i = beg; i < end; i++) {
        unsigned p = (unsigned)__ldg(pay + i);
        int s = (int)(p & 0x0FFFFFFFu);
        int t = (int)(p >> 28);
        const fp162* src = (const fp162*)(H + (size_t)s * 128 + j);
        float2 f0 = __half22float2(src[0]);
        float2 f1 = __half22float2(src[1]);
        if (t == 0)      { a[0][0] += f0.x; a[0][1] += f0.y; a[0][2] += f1.x; a[0][3] += f1.y; d0++; }
        else if (t == 1) { a[1][0] += f0.x; a[1][1] += f0.y; a[1][2] += f1.x; a[1][3] += f1.y; d1++; }
        else             { a[2][0] += f0.x; a[2][1] += f0.y; a[2][2] += f1.x; a[2][3] += f1.y; d2++; }
    }
    size_t base = (size_t)w * KAGG;
#pragma unroll
    for (int t = 0; t < 3; t++) {
        fp162* dst = (fp162*)(AGG + base + t * 128 + j);
        dst[0] = __floats2half2_rn(a[t][0], a[t][1]);
        dst[1] = __floats2half2_rn(a[t][2], a[t][3]);
    }
    if (lane < 8) {
        fp162* dst = (fp162*)(AGG + base + 384 + lane * 4);
        fp162 z = __floats2half2_rn(0.f, 0.f);
        dst[0] = z; dst[1] = z;
    }
    __syncwarp();
    if (lane == 0) {
        AGG[base + 384] = __float2half_rn((float)d0);
        AGG[base + 385] = __float2half_rn((float)d1);
        AGG[base + 386] = __float2half_rn((float)d2);
    }
}

// ------------------------- cp.async helpers -------------------------
__device__ __forceinline__ void cp16(uint32_t dst, const void* src, int sz) {
    asm volatile("cp.async.cg.shared.global [%0], [%1], 16, %2;" :: "r"(dst), "l"(src), "r"(sz));
}
__device__ __forceinline__ void cp_commit() { asm volatile("cp.async.commit_group;"); }
__device__ __forceinline__ void cp_wait0() { asm volatile("cp.async.wait_group 0;"); }
__device__ __forceinline__ void cp_wait1() { asm volatile("cp.async.wait_group 1;"); }

__device__ __forceinline__ void ldm_x4(uint32_t addr, uint32_t& r0, uint32_t& r1, uint32_t& r2, uint32_t& r3) {
    asm volatile("ldmatrix.sync.aligned.m8n8.x4.shared.b16 {%0,%1,%2,%3}, [%4];"
                 : "=r"(r0), "=r"(r1), "=r"(r2), "=r"(r3) : "r"(addr));
}

#define MMA16(d, a, b)                                                                             \
    asm volatile("mma.sync.aligned.m16n8k16.row.col.f32.f16.f16.f32 "                             \
                 "{%0,%1,%2,%3},{%4,%5,%6,%7},{%8,%9},{%0,%1,%2,%3};"                             \
                 : "+f"(d[0]), "+f"(d[1]), "+f"(d[2]), "+f"(d[3])                                  \
                 : "r"(a[0]), "r"(a[1]), "r"(a[2]), "r"(a[3]), "r"(b[0]), "r"(b[1]))

// smem geometry (halves)
#define MM_STR 40
#define MM_STAGE_HALVES (128 * MM_STR)
#define MM_SMEM_HALVES  (3 * 2 * MM_STAGE_HALVES)
#define MM_SMEM_BYTES   (MM_SMEM_HALVES * 2)             // 61440

// ------------------------- unified fp16 tensor-core GEMM -------------------------
// 256 threads, 8 warps, warp tile 32x64 (champion geometry).
// Y[M,N] = X[M,K] @ W[N,K]^T (+ bias)
// XMODE: 0 plain (stride=K), 1 [MSG|Ch], 2 [MSG|flip|H], 3 [L[:NV]|L[NV:]]
// EPI:   0 bias-store, 1 bias-relu-store, 2 fused LSTM cell (gate-permuted weights, fp16 c)
// GSWAP: 1 -> (m,n)=(by,bx): n-blocks schedule-adjacent for L2 X reuse
// 3-stage cp.async ring, ONE __syncthreads per K-iter.
template <int XMODE, int EPI, int K, int GSWAP>
__global__ void __launch_bounds__(256, 2) mm_kernel(
    const fp16* __restrict__ X0, const fp16* __restrict__ X1,
    const fp16* __restrict__ W, const float* __restrict__ bias,
    fp16* __restrict__ Y, int ldY,
    const fp16* __restrict__ Cold, fp16* __restrict__ Hnew, fp16* __restrict__ Cnew,
    int M) {
    extern __shared__ __align__(16) fp16 smraw[];
    fp16* xs = smraw;                          // [3][128][MM_STR]
    fp16* ws = smraw + 3 * MM_STAGE_HALVES;    // [3][128][MM_STR]
    const int tid = threadIdx.x;
    const int lane = tid & 31, warp = tid >> 5;
    const int wm = warp & 3, wn = warp >> 2;
    const int mblk = GSWAP ? blockIdx.y : blockIdx.x;
    const int nblk = GSWAP ? blockIdx.x : blockIdx.y;
    const int row0 = mblk * 128, n0 = nblk * 128;
    const uint32_t xs_u = (uint32_t)__cvta_generic_to_shared(xs);
    const uint32_t ws_u = (uint32_t)__cvta_generic_to_shared(ws);

    float acc[2][8][4];
#pragma unroll
    for (int a = 0; a < 2; a++)
#pragma unroll
        for (int b = 0; b < 8; b++)
#pragma unroll
            for (int c = 0; c < 4; c++) acc[a][b][c] = 0.0f;

    auto load_tiles = [&](int it, int buf) {
        int kb = it * 32;
        uint32_t xbase = xs_u + (uint32_t)(buf * MM_STAGE_HALVES * 2);
        uint32_t wbase = ws_u + (uint32_t)(buf * MM_STAGE_HALVES * 2);
#pragma unroll
        for (int q = 0; q < 2; q++) {
            int chunk = tid + 256 * q;
            int r = chunk >> 2, cc = chunk & 3;
            int gr = row0 + r;
            int grc = gr < M ? gr : (M - 1);
            int gk = kb + cc * 8;
            const fp16* src;
            if (XMODE == 0) {
                src = X0 + (size_t)grc * K + gk;
            } else if (XMODE == 1) {
                src = (gk < 128) ? X0 + (size_t)grc * 128 + gk
                                 : X1 + (size_t)grc * 128 + (gk - 128);
            } else if (XMODE == 2) {
                if (gk < 128) src = X0 + (size_t)grc * 128 + gk;
                else if (gk < 256) {
                    int fr = (grc < NV) ? grc + NV : grc - NV;
                    src = X1 + (size_t)fr * 128 + (gk - 128);
                } else src = X1 + (size_t)grc * 128 + (gk - 256);
            } else {  // XMODE 3
                src = (gk < 128) ? X0 + (size_t)grc * 128 + gk
                                 : X0 + (size_t)(grc + NV) * 128 + (gk - 128);
            }
            cp16(xbase + (uint32_t)((r * MM_STR + cc * 8) * 2), src, gr < M ? 16 : 0);
        }
#pragma unroll
        for (int q = 0; q < 2; q++) {
            int chunk = tid + 256 * q;
            int n = chunk >> 2, cc = chunk & 3;
            const fp16* src = W + (size_t)(n0 + n) * K + kb + cc * 8;
            cp16(wbase + (uint32_t)((n * MM_STR + cc * 8) * 2), src, 16);
        }
        cp_commit();
    };

    auto compute = [&](int buf) {
        uint32_t xbase = xs_u + (uint32_t)(buf * MM_STAGE_HALVES * 2);
        uint32_t wbase = ws_u + (uint32_t)(buf * MM_STAGE_HALVES * 2);
#pragma unroll
        for (int ks = 0; ks < 2; ks++) {
            int coloff = ks * 16 + ((lane >> 4) & 1) * 8;
            uint32_t afrag[2][4];
#pragma unroll
            for (int mt = 0; mt < 2; mt++) {
                int r = wm * 32 + mt * 16 + (lane & 15);
                uint32_t addr = xbase + (uint32_t)((r * MM_STR + coloff) * 2);
                ldm_x4(addr, afrag[mt][0], afrag[mt][1], afrag[mt][2], afrag[mt][3]);
            }
            uint32_t bfrag[8][2];
#pragma unroll
            for (int p = 0; p < 4; p++) {
                int n = wn * 64 + p * 16 + (lane & 15);
                uint32_t addr = wbase + (uint32_t)((n * MM_STR + coloff) * 2);
                uint32_t r0, r1, r2, r3;
                ldm_x4(addr, r0, r1, r2, r3);
                bfrag[2 * p][0] = r0; bfrag[2 * p][1] = r2;
                bfrag[2 * p + 1][0] = r1; bfrag[2 * p + 1][1] = r3;
            }
#pragma unroll
            for (int mt = 0; mt < 2; mt++)
#pragma unroll
                for (int nt = 0; nt < 8; nt++) MMA16(acc[mt][nt], afrag[mt], bfrag[nt]);
        }
    };

    constexpr int ITERS = K / 32;
    load_tiles(0, 0);
    load_tiles(1, 1);
    for (int it = 0; it < ITERS; it++) {
        if (it + 1 < ITERS) cp_wait1(); else cp_wait0();
        __syncthreads();
        if (it + 2 < ITERS) load_tiles(it + 2, (it + 2) % 3);
        compute(it % 3);
    }
    __syncthreads();   // protect epilogue smem reuse from lagging warps

    if (EPI == 0 || EPI == 1) {
#pragma unroll
        for (int mt = 0; mt < 2; mt++) {
#pragma unroll
            for (int nt = 0; nt < 8; nt++) {
                int gr0 = row0 + wm * 32 + mt * 16 + (lane >> 2);
                int col = n0 + wn * 64 + nt * 8 + 2 * (lane & 3);
                float b0v = __ldg(bias + col), b1v = __ldg(bias + col + 1);
                float v0 = acc[mt][nt][0] + b0v, v1 = acc[mt][nt][1] + b1v;
                float v2 = acc[mt][nt][2] + b0v, v3 = acc[mt][nt][3] + b1v;
                if (EPI == 1) {
                    v0 = fmaxf(v0, 0.f); v1 = fmaxf(v1, 0.f);
                    v2 = fmaxf(v2, 0.f); v3 = fmaxf(v3, 0.f);
                }
                if (gr0 < M)
                    *(fp162*)(Y + (size_t)gr0 * ldY + col) = __floats2half2_rn(v0, v1);
                if (gr0 + 8 < M)
                    *(fp162*)(Y + (size_t)(gr0 + 8) * ldY + col) = __floats2half2_rn(v2, v3);
            }
        }
    } else {
        // fused LSTM epilogue; this block handles kk in [nblk*32, +32); fp16 cell state
        const int kk0 = nblk * 32;
        float* cs = (float*)smraw;        // [128][33]
        float* hs = cs + 128 * 33;        // [128][33]
        for (int i = tid; i < 1024; i += 256) {
            int r = i >> 3, c = (i & 7) * 4;
            int gr = row0 + r;
            if (gr < M) {
                const fp162* cp = (const fp162*)(Cold + (size_t)gr * 128 + kk0 + c);
                float2 va = __half22float2(cp[0]);
                float2 vb = __half22float2(cp[1]);
                cs[r * 33 + c + 0] = va.x; cs[r * 33 + c + 1] = va.y;
                cs[r * 33 + c + 2] = vb.x; cs[r * 33 + c + 3] = vb.y;
            }
        }
        __syncthreads();
        const int odd = lane & 1;
#pragma unroll
        for (int nt = 0; nt < 8; nt++) {
            int colp = wn * 64 + nt * 8 + 2 * (lane & 3);
            float b0v = __ldg(bias + n0 + colp), b1v = __ldg(bias + n0 + colp + 1);
            int kkl = colp >> 2;
#pragma unroll
            for (int mt = 0; mt < 2; mt++) {
                float c0 = acc[mt][nt][0] + b0v, c1 = acc[mt][nt][1] + b1v;
                float c2 = acc[mt][nt][2] + b0v, c3 = acc[mt][nt][3] + b1v;
                float x0 = __shfl_xor_sync(0xffffffffu, c0, 1);
                float x1 = __shfl_xor_sync(0xffffffffu, c1, 1);
                float x2 = __shfl_xor_sync(0xffffffffu, c2, 1);
                float x3 = __shfl_xor_sync(0xffffffffu, c3, 1);
                float gi = odd ? x2 : c0;
                float gf = odd ? x3 : c1;
                float gg = odd ? c2 : x0;
                float go = odd ? c3 : x1;
                int rloc = wm * 32 + mt * 16 + (lane >> 2) + odd * 8;
                float cold = cs[rloc * 33 + kkl];
                float c2v = sigmoid_fast(gf) * cold + sigmoid_fast(gi) * tanh_fast(gg);
                float h = sigmoid_fast(go) * tanh_fast(c2v);
                cs[rloc * 33 + kkl] = c2v;
                hs[rloc * 33 + kkl] = h;
            }
        }
        __syncthreads();
        for (int i = tid; i < 1024; i += 256) {
            int r = i >> 3, c = (i & 7) * 4;
            int gr = row0 + r;
            if (gr < M) {
                fp162* cd = (fp162*)(Cnew + (size_t)gr * 128 + kk0 + c);
                cd[0] = __floats2half2_rn(cs[r * 33 + c], cs[r * 33 + c + 1]);
                cd[1] = __floats2half2_rn(cs[r * 33 + c + 2], cs[r * 33 + c + 3]);
                fp162* hp = (fp162*)(Hnew + (size_t)gr * 128 + kk0 + c);
                hp[0] = __floats2half2_rn(hs[r * 33 + c], hs[r * 33 + c + 1]);
                hp[1] = __floats2half2_rn(hs[r * 33 + c + 2], hs[r * 33 + c + 3]);
            }
        }
    }
}

// ------------------------- final vote -------------------------
__global__ void vote_kernel(const fp16* __restrict__ H2, const float* __restrict__ w3,
                            const float* __restrict__ b3, float* __restrict__ out, int M) {
    int w = (blockIdx.x * blockDim.x + threadIdx.x) >> 5;
    int lane = threadIdx.x & 31;
    if (w < M) {
        float s = 0.0f;
#pragma unroll
        for (int q = 0; q < 4; q++) {
            int j = lane + 32 * q;
            s += __half2float(H2[(size_t)w * 128 + j]) * __ldg(w3 + j);
        }
#pragma unroll
        for (int o = 16; o > 0; o >>= 1) s += __shfl_xor_sync(0xffffffffu, s, o);
        if (lane == 0) out[w] = s + b3[0];
    }
}

// ------------------------- host orchestration -------------------------
static void build_csr(const int* src0, const int* dst0, int E0,
                      const int* src1, const int* dst1, int E1,
                      const int* src2, const int* dst2, int E2,
                      int ndst, int* offs, int* pay,
                      int* cnt, int* cur, int* exsc, int* blksum) {
    zero_int_kernel<<<(ndst + 255) / 256, 256>>>(cnt, ndst);
    hist_kernel<<<(E0 + 255) / 256, 256>>>(dst0, E0, cnt);
    hist_kernel<<<(E1 + 255) / 256, 256>>>(dst1, E1, cnt);
    hist_kernel<<<(E2 + 255) / 256, 256>>>(dst2, E2, cnt);
    int nb = (ndst + 1023) / 1024;
    scanA_kernel<<<nb, 1024>>>(cnt, exsc, blksum, ndst);
    scanB_kernel<<<1, 32>>>(blksum, nb);
    scanC_kernel<<<(ndst + 255) / 256, 256>>>(exsc, blksum, offs, ndst, E0 + E1 + E2);
    zero_int_kernel<<<(ndst + 255) / 256, 256>>>(cur, ndst);
    fill_csr_kernel<<<(E0 + 255) / 256, 256>>>(src0, dst0, E0, 0, offs, cur, pay);
    fill_csr_kernel<<<(E1 + 255) / 256, 256>>>(src1, dst1, E1, 1, offs, cur, pay);
    fill_csr_kernel<<<(E2 + 255) / 256, 256>>>(src2, dst2, E2, 2, offs, cur, pay);
}

extern "C" void kernel_launch(void* const* d_in, const int* in_sizes, int n_in,
                              void* d_out, int out_size) {
    (void)in_sizes; (void)n_in; (void)out_size;
    const float* l_init_w   = (const float*)d_in[0];
    const float* l_init_b   = (const float*)d_in[1];
    const float* c_init_w   = (const float*)d_in[2];
    const float* c_init_b   = (const float*)d_in[3];
    const float* mha_in_w   = (const float*)d_in[4];
    const float* mha_in_b   = (const float*)d_in[5];
    const float* mha_out_w  = (const float*)d_in[6];
    const float* mha_out_b  = (const float*)d_in[7];
    const float* lstm_L_wih = (const float*)d_in[8];
    const float* lstm_L_whh = (const float*)d_in[9];
    const float* lstm_L_bih = (const float*)d_in[10];
    const float* lstm_L_bhh = (const float*)d_in[11];
    const float* lstm_C_wih = (const float*)d_in[12];
    const float* lstm_C_whh = (const float*)d_in[13];
    const float* lstm_C_bih = (const float*)d_in[14];
    const float* lstm_C_bhh = (const float*)d_in[15];
    const float* mlp_w1     = (const float*)d_in[16];
    const float* mlp_b1     = (const float*)d_in[17];
    const float* mlp_w2     = (const float*)d_in[18];
    const float* mlp_b2     = (const float*)d_in[19];
    const float* mlp_w3     = (const float*)d_in[20];
    const float* mlp_b3     = (const float*)d_in[21];
    const int* child_lit    = (const int*)d_in[22];
    const int* child_clause = (const int*)d_in[23];
    const int* fa_lit       = (const int*)d_in[24];
    const int* fa_clause    = (const int*)d_in[25];
    const int* nt_lit       = (const int*)d_in[26];
    const int* nt_clause    = (const int*)d_in[27];

    fp16 *Lh0, *Lh1, *Lc, *Ch0, *Ch1, *Cc, *MSG, *G, *AGG, *WgatC, *WcatL, *WC, *WL, *W1, *W2;
    float *Weff, *beff, *bC, *bL, *zeroB;
    int *offsLC, *offsCL, *payLC, *payCL, *cnt, *cur, *exsc, *blksum;
    cudaGetSymbolAddress((void**)&Lh0, g_Lh0);
    cudaGetSymbolAddress((void**)&Lh1, g_Lh1);
    cudaGetSymbolAddress((void**)&Lc,  g_Lc);
    cudaGetSymbolAddress((void**)&Ch0, g_Ch0);
    cudaGetSymbolAddress((void**)&Ch1, g_Ch1);
    cudaGetSymbolAddress((void**)&Cc,  g_Cc);
    cudaGetSymbolAddress((void**)&MSG, g_MSG);
    cudaGetSymbolAddress((void**)&G,   g_G);
    cudaGetSymbolAddress((void**)&AGG, g_AGG);
    cudaGetSymbolAddress((void**)&Weff, g_Weff);
    cudaGetSymbolAddress((void**)&beff, g_beff);
    cudaGetSymbolAddress((void**)&WgatC, g_WgatC);
    cudaGetSymbolAddress((void**)&WcatL, g_WcatL);
    cudaGetSymbolAddress((void**)&WC, g_WC);
    cudaGetSymbolAddress((void**)&bC, g_bC);
    cudaGetSymbolAddress((void**)&WL, g_WL);
    cudaGetSymbolAddress((void**)&bL, g_bL);
    cudaGetSymbolAddress((void**)&W1, g_W1);
    cudaGetSymbolAddress((void**)&W2, g_W2);
    cudaGetSymbolAddress((void**)&zeroB, g_zero);
    cudaGetSymbolAddress((void**)&offsLC, g_offsLC);
    cudaGetSymbolAddress((void**)&offsCL, g_offsCL);
    cudaGetSymbolAddress((void**)&payLC, g_payLC);
    cudaGetSymbolAddress((void**)&payCL, g_payCL);
    cudaGetSymbolAddress((void**)&cnt, g_cnt);
    cudaGetSymbolAddress((void**)&cur, g_cur);
    cudaGetSymbolAddress((void**)&exsc, g_exsc);
    cudaGetSymbolAddress((void**)&blksum, g_blksum);

    cudaFuncSetAttribute(mm_kernel<0, 0, 128, 1>, cudaFuncAttributeMaxDynamicSharedMemorySize, MM_SMEM_BYTES);
    cudaFuncSetAttribute(mm_kernel<1, 2, 256, 1>, cudaFuncAttributeMaxDynamicSharedMemorySize, MM_SMEM_BYTES);
    cudaFuncSetAttribute(mm_kernel<0, 0, KAGG, 0>, cudaFuncAttributeMaxDynamicSharedMemorySize, MM_SMEM_BYTES);
    cudaFuncSetAttribute(mm_kernel<2, 2, 384, 1>, cudaFuncAttributeMaxDynamicSharedMemorySize, MM_SMEM_BYTES);
    cudaFuncSetAttribute(mm_kernel<3, 1, 256, 0>, cudaFuncAttributeMaxDynamicSharedMemorySize, MM_SMEM_BYTES);
    cudaFuncSetAttribute(mm_kernel<0, 1, 128, 0>, cudaFuncAttributeMaxDynamicSharedMemorySize, MM_SMEM_BYTES);

    // ---- setup ----
    compute_weff_kernel<<<dim3(128, 6), 128>>>(mha_in_w, mha_in_b, mha_out_w, mha_out_b, Weff, beff);
    prep_wgat_kernel<<<384, 128>>>(Weff, WgatC);
    prep_wcatL_kernel<<<128, KAGG>>>(Weff, beff, WcatL);
    prep_lstm_kernel<<<512, 256>>>(lstm_C_wih, lstm_C_whh, lstm_C_bih, lstm_C_bhh, WC, bC, 128);
    prep_lstm_kernel<<<512, 384>>>(lstm_L_wih, lstm_L_whh, lstm_L_bih, lstm_L_bhh, WL, bL, 256);
    prep_mlp_kernel<<<(128 * 256 + 255) / 256, 256>>>(mlp_w1, mlp_w2, W1, W2);
    init_state_kernel<<<(int)(((size_t)NC * DIM + 255) / 256), 256>>>(
        l_init_w, l_init_b, c_init_w, c_init_b, Lh0, Lc, Ch0, Cc);

    build_csr(child_lit, child_clause, ECNT, fa_lit, fa_clause, EFNT, nt_lit, nt_clause, ENNT,
              NC, offsLC, payLC, cnt, cur, exsc, blksum);
    build_csr(child_clause, child_lit, ECNT, fa_clause, fa_lit, EFNT, nt_clause, nt_lit, ENNT,
              NL, offsCL, payCL, cnt, cur, exsc, blksum);

    fp16* Lcur = Lh0; fp16* Lnxt = Lh1;
    fp16* Ccur = Ch0; fp16* Cnxt = Ch1;

    const int GB_L = (NL + 127) / 128;   // 782
    const int GB_C = (NC + 127) / 128;   // 1641
    const int GB_V = (NV + 127) / 128;   // 391

    for (int r = 0; r < ROUNDS; r++) {
        // ---- L -> C: transform L (small side), gather-aggregate into MSG ----
        mm_kernel<0, 0, 128, 1><<<dim3(3, GB_L), 256, MM_SMEM_BYTES>>>(
            Lcur, nullptr, WgatC, zeroB, G, 384, nullptr, nullptr, nullptr, NL);
        aggL2C_kernel<<<(NC * 32 + 255) / 256, 256>>>(payLC, offsLC, G, beff, MSG, NC);
        mm_kernel<1, 2, 256, 1><<<dim3(4, GB_C), 256, MM_SMEM_BYTES>>>(
            MSG, Ccur, WC, bC, nullptr, 0, Cc, Cnxt, Cc, NC);
        { fp16* t = Ccur; Ccur = Cnxt; Cnxt = t; }

        // ---- C -> L: aggregate C (small dst side), then transform ----
        aggC2L_kernel<<<(NL * 32 + 255) / 256, 256>>>(payCL, offsCL, Ccur, AGG, NL);
        mm_kernel<0, 0, KAGG, 0><<<dim3(GB_L, 1), 256, MM_SMEM_BYTES>>>(
            AGG, nullptr, WcatL, zeroB, MSG, 128, nullptr, nullptr, nullptr, NL);
        mm_kernel<2, 2, 384, 1><<<dim3(4, GB_L), 256, MM_SMEM_BYTES>>>(
            MSG, Lcur, WL, bL, nullptr, 0, Lc, Lnxt, Lc, NL);
        { fp16* t = Lcur; Lcur = Lnxt; Lnxt = t; }
    }

    // ---- final MLP ----
    mm_kernel<3, 1, 256, 0><<<dim3(GB_V, 1), 256, MM_SMEM_BYTES>>>(
        Lcur, nullptr, W1, mlp_b1, G, 128, nullptr, nullptr, nullptr, NV);
    mm_kernel<0, 1, 128, 0><<<dim3(GB_V, 1), 256, MM_SMEM_BYTES>>>(
        G, nullptr, W2, mlp_b2, MSG, 128, nullptr, nullptr, nullptr, NV);
    vote_kernel<<<(NV * 32 + 255) / 256, 256>>>(MSG, mlp_w3, mlp_b3, (float*)d_out, NV);
}

// round 12
// speedup vs baseline: 1.5091x; 1.0054x over previous
#include <cuda_runtime.h>
#include <cuda_fp16.h>
#include <math.h>
#include <stdint.h>

#define DIM 128
#define NV 50000
#define NL 100000
#define NC 210000
#define ECNT 300000
#define EFNT 100000
#define ENNT 200000
#define ETOT 600000
#define ROUNDS 8
#define KAGG 416   // 384 sums + 3 deg + 29 zero pad (multiple of 32)

typedef __half fp16;
typedef __half2 fp162;

// ------------------------- static device scratch -------------------------
__device__ fp16  g_Lh0[(size_t)NL * DIM];
__device__ fp16  g_Lh1[(size_t)NL * DIM];
__device__ fp16  g_Lc [(size_t)NL * DIM];
__device__ fp16  g_Ch0[(size_t)NC * DIM];
__device__ fp16  g_Ch1[(size_t)NC * DIM];
__device__ fp16  g_Cc [(size_t)NC * DIM];
__device__ fp16  g_MSG[(size_t)NC * DIM];
__device__ fp16  g_G  [(size_t)NL * 384];
__device__ fp16  g_AGG[(size_t)NL * KAGG];
__device__ fp16  g_BIASC[(size_t)NC * DIM];
__device__ float g_Weff[6 * DIM * DIM];
__device__ float g_beff[6 * DIM];
__device__ fp16  g_WgatC[384 * DIM];
__device__ fp16  g_WcatL[DIM * KAGG];
__device__ fp16  g_WC[512 * 256];
__device__ float g_bC[512];
__device__ fp16  g_WL[512 * 384];
__device__ float g_bL[512];
__device__ fp16  g_W1[128 * 256];
__device__ fp16  g_W2[128 * 128];
__device__ float g_zero[512];
// CSR scratch
__device__ int g_offsLC[NC + 1];
__device__ int g_offsCL[NL + 1];
__device__ int g_payLC[ETOT];
__device__ int g_payCL[ETOT];
__device__ int g_cnt[NC];
__device__ int g_cur[NC];
__device__ int g_exsc[NC];
__device__ int g_blksum[256];

__device__ __forceinline__ float sigmoidf_(float x) { return 1.0f / (1.0f + __expf(-x)); }

// fast transcendental path for LSTM epilogue (MUFU.TANH, sm_75+)
__device__ __forceinline__ float tanh_fast(float x) {
    float y;
    asm("tanh.approx.f32 %0, %1;" : "=f"(y) : "f"(x));
    return y;
}
__device__ __forceinline__ float sigmoid_fast(float x) {
    return fmaf(tanh_fast(0.5f * x), 0.5f, 0.5f);
}

// ------------------------- weff precompute (fp32) -------------------------
__global__ void compute_weff_kernel(const float* __restrict__ mha_in_w,
                                    const float* __restrict__ mha_in_b,
                                    const float* __restrict__ mha_out_w,
                                    const float* __restrict__ mha_out_b,
                                    float* __restrict__ Weff,
                                    float* __restrict__ beff) {
    int o = blockIdx.x, t = blockIdx.y, v = threadIdx.x;
    const float* Wo = mha_out_w + (size_t)t * DIM * DIM + (size_t)o * DIM;
    const float* Wv = mha_in_w + (size_t)t * 3 * DIM * DIM + (size_t)2 * DIM * DIM;
    float acc = 0.0f;
#pragma unroll 8
    for (int j = 0; j < DIM; j++) acc += Wo[j] * Wv[(size_t)j * DIM + v];
    Weff[((size_t)t * DIM + o) * DIM + v] = acc;
    if (v == 0) {
        const float* bv = mha_in_b + t * 3 * DIM + 2 * DIM;
        float s = 0.0f;
        for (int j = 0; j < DIM; j++) s += Wo[j] * bv[j];
        beff[t * DIM + o] = s + mha_out_b[t * DIM + o];
    }
}

__global__ void prep_wgat_kernel(const float* __restrict__ Weff, fp16* __restrict__ Wg) {
    int n = blockIdx.x, k = threadIdx.x;
    Wg[(size_t)n * 128 + k] = __float2half_rn(Weff[(size_t)n * 128 + k]);
}

__global__ void prep_wcatL_kernel(const float* __restrict__ Weff, const float* __restrict__ beff,
                                  fp16* __restrict__ Wc) {
    int n = blockIdx.x, k = threadIdx.x;   // 0..415
    float v;
    if (k < 384) {
        int t = k >> 7, j = k & 127;
        v = Weff[(((size_t)(3 + t)) * DIM + n) * DIM + j];
    } else if (k < 387) {
        v = beff[(3 + (k - 384)) * DIM + n];
    } else v = 0.0f;
    Wc[(size_t)n * KAGG + k] = __float2half_rn(v);
}

__global__ void prep_lstm_kernel(const float* __restrict__ wih, const float* __restrict__ whh,
                                 const float* __restrict__ bih, const float* __restrict__ bhh,
                                 fp16* __restrict__ Wd, float* __restrict__ bd, int KX) {
    int n = blockIdx.x, k = threadIdx.x;
    int K = KX + 128;
    int orig = (n & 3) * 128 + (n >> 2);
    float v = (k < KX) ? wih[(size_t)orig * KX + k] : whh[(size_t)orig * 128 + (k - KX)];
    Wd[(size_t)n * K + k] = __float2half_rn(v);
    if (k == 0) bd[n] = bih[orig] + bhh[orig];
}

__global__ void prep_mlp_kernel(const float* __restrict__ w1, const float* __restrict__ w2,
                                fp16* __restrict__ W1r, fp16* __restrict__ W2r) {
    int i = blockIdx.x * blockDim.x + threadIdx.x;
    if (i < 128 * 256) W1r[i] = __float2half_rn(w1[i]);
    if (i < 128 * 128) W2r[i] = __float2half_rn(w2[i]);
}

__global__ void init_state_kernel(const float* __restrict__ lw, const float* __restrict__ lb,
                                  const float* __restrict__ cw, const float* __restrict__ cb,
                                  fp16* __restrict__ Lh, fp16* __restrict__ Lc,
                                  fp16* __restrict__ Ch, fp16* __restrict__ Cc) {
    size_t idx = (size_t)blockIdx.x * blockDim.x + threadIdx.x;
    int j = (int)(idx & (DIM - 1));
    fp16 z = __float2half_rn(0.0f);
    if (idx < (size_t)NL * DIM) { Lh[idx] = __float2half_rn(lw[j] + lb[j]); Lc[idx] = z; }
    if (idx < (size_t)NC * DIM) { Ch[idx] = __float2half_rn(cw[j] + cb[j]); Cc[idx] = z; }
}

// ------------------------- CSR build -------------------------
__global__ void zero_int_kernel(int* __restrict__ p, int n) {
    int i = blockIdx.x * blockDim.x + threadIdx.x;
    if (i < n) p[i] = 0;
}
__global__ void hist_kernel(const int* __restrict__ dst, int E, int* __restrict__ cnt) {
    int e = blockIdx.x * blockDim.x + threadIdx.x;
    if (e < E) atomicAdd(&cnt[dst[e]], 1);
}
__global__ void scanA_kernel(const int* __restrict__ cnt, int* __restrict__ exsc,
                             int* __restrict__ blksum, int n) {
    __shared__ int sm[1024];
    int tid = threadIdx.x;
    int i = blockIdx.x * 1024 + tid;
    int v = (i < n) ? cnt[i] : 0;
    sm[tid] = v;
    __syncthreads();
    for (int o = 1; o < 1024; o <<= 1) {
        int t = (tid >= o) ? sm[tid - o] : 0;
        __syncthreads();
        sm[tid] += t;
        __syncthreads();
    }
    if (i < n) exsc[i] = sm[tid] - v;
    if (tid == 1023) blksum[blockIdx.x] = sm[1023];
}
__global__ void scanB_kernel(int* __restrict__ blksum, int nb) {
    if (threadIdx.x == 0 && blockIdx.x == 0) {
        int s = 0;
        for (int b = 0; b < nb; b++) { int t = blksum[b]; blksum[b] = s; s += t; }
    }
}
__global__ void scanC_kernel(const int* __restrict__ exsc, const int* __restrict__ blksum,
                             int* __restrict__ offs, int n, int E) {
    int i = blockIdx.x * blockDim.x + threadIdx.x;
    if (i < n) offs[i] = exsc[i] + blksum[i >> 10];
    if (i == 0) offs[n] = E;
}
__global__ void fill_csr_kernel(const int* __restrict__ src, const int* __restrict__ dst, int E,
                                int type, const int* __restrict__ offs, int* __restrict__ cur,
                                int* __restrict__ pay) {
    int e = blockIdx.x * blockDim.x + threadIdx.x;
    if (e < E) {
        int d = dst[e];
        int pos = offs[d] + atomicAdd(&cur[d], 1);
        pay[pos] = src[e] | (type << 28);
    }
}

// ------------------------- round-invariant precompute -------------------------
// BIASC[c][j] = sum_t deg_t(c) * beff[t][j]   (one warp per clause, once per launch)
__global__ void prep_biasC_kernel(const int* __restrict__ pay, const int* __restrict__ offs,
                                  const float* __restrict__ beff, fp16* __restrict__ BIASC,
                                  int ndst) {
    int w = (blockIdx.x * blockDim.x + threadIdx.x) >> 5;
    int lane = threadIdx.x & 31;
    if (w >= ndst) return;
    int beg = offs[w], end = offs[w + 1];
    int d0 = 0, d1 = 0, d2 = 0;
    for (int i = beg; i < end; i++) {
        int t = (int)((unsigned)pay[i] >> 28);
        d0 += (t == 0); d1 += (t == 1); d2 += (t == 2);
    }
    float f0 = (float)d0, f1 = (float)d1, f2 = (float)d2;
    int j = lane * 4;
    float b0 = f0 * beff[j + 0] + f1 * beff[128 + j + 0] + f2 * beff[256 + j + 0];
    float b1 = f0 * beff[j + 1] + f1 * beff[128 + j + 1] + f2 * beff[256 + j + 1];
    float b2 = f0 * beff[j + 2] + f1 * beff[128 + j + 2] + f2 * beff[256 + j + 2];
    float b3 = f0 * beff[j + 3] + f1 * beff[128 + j + 3] + f2 * beff[256 + j + 3];
    fp162* dst = (fp162*)(BIASC + (size_t)w * 128 + j);
    dst[0] = __floats2half2_rn(b0, b1);
    dst[1] = __floats2half2_rn(b2, b3);
}

// AGG pad + degree cols (384..415) are round-invariant: write once per launch.
__global__ void prep_aggpad_kernel(const int* __restrict__ pay, const int* __restrict__ offs,
                                   fp16* __restrict__ AGG, int ndst) {
    int w = (blockIdx.x * blockDim.x + threadIdx.x) >> 5;
    int lane = threadIdx.x & 31;
    if (w >= ndst) return;
    int beg = offs[w], end = offs[w + 1];
    int d0 = 0, d1 = 0, d2 = 0;
    for (int i = beg; i < end; i++) {
        int t = (int)((unsigned)pay[i] >> 28);
        d0 += (t == 0); d1 += (t == 1); d2 += (t == 2);
    }
    size_t base = (size_t)w * KAGG;
    if (lane < 8) {
        fp162* dst = (fp162*)(AGG + base + 384 + lane * 4);
        fp162 z = __floats2half2_rn(0.f, 0.f);
        dst[0] = z; dst[1] = z;
    }
    __syncwarp();
    if (lane == 0) {
        AGG[base + 384] = __float2half_rn((float)d0);
        AGG[base + 385] = __float2half_rn((float)d1);
        AGG[base + 386] = __float2half_rn((float)d2);
    }
}

// ------------------------- aggregation kernels (2-way unrolled gathers) -------------------------
__global__ void aggL2C_kernel(const int* __restrict__ pay, const int* __restrict__ offs,
                              const fp16* __restrict__ G, const fp16* __restrict__ BIASC,
                              fp16* __restrict__ MSG, int ndst) {
    int w = (blockIdx.x * blockDim.x + threadIdx.x) >> 5;
    int lane = threadIdx.x & 31;
    if (w >= ndst) return;
    int beg = offs[w], end = offs[w + 1];
    float a0 = 0.f, a1 = 0.f, a2 = 0.f, a3 = 0.f;
    int j = lane * 4;
    int i = beg;
    for (; i + 1 < end; i += 2) {
        unsigned p0 = (unsigned)__ldg(pay + i);
        unsigned p1 = (unsigned)__ldg(pay + i + 1);
        const fp162* s0 = (const fp162*)(G + (size_t)(p0 & 0x0FFFFFFFu) * 384 + (p0 >> 28) * 128 + j);
        const fp162* s1 = (const fp162*)(G + (size_t)(p1 & 0x0FFFFFFFu) * 384 + (p1 >> 28) * 128 + j);
        fp162 u00 = s0[0], u01 = s0[1];
        fp162 u10 = s1[0], u11 = s1[1];
        float2 f00 = __half22float2(u00), f01 = __half22float2(u01);
        float2 f10 = __half22float2(u10), f11 = __half22float2(u11);
        a0 += f00.x + f10.x; a1 += f00.y + f10.y;
        a2 += f01.x + f11.x; a3 += f01.y + f11.y;
    }
    if (i < end) {
        unsigned p = (unsigned)__ldg(pay + i);
        const fp162* s = (const fp162*)(G + (size_t)(p & 0x0FFFFFFFu) * 384 + (p >> 28) * 128 + j);
        float2 f0 = __half22float2(s[0]);
        float2 f1 = __half22float2(s[1]);
        a0 += f0.x; a1 += f0.y; a2 += f1.x; a3 += f1.y;
    }
    const fp162* bp = (const fp162*)(BIASC + (size_t)w * 128 + j);
    float2 bb0 = __half22float2(bp[0]);
    float2 bb1 = __half22float2(bp[1]);
    a0 += bb0.x; a1 += bb0.y; a2 += bb1.x; a3 += bb1.y;
    fp162* dst = (fp162*)(MSG + (size_t)w * 128 + j);
    dst[0] = __floats2half2_rn(a0, a1);
    dst[1] = __floats2half2_rn(a2, a3);
}

__global__ void aggC2L_kernel(const int* __restrict__ pay, const int* __restrict__ offs,
                              const fp16* __restrict__ H, fp16* __restrict__ AGG, int ndst) {
    int w = (blockIdx.x * blockDim.x + threadIdx.x) >> 5;
    int lane = threadIdx.x & 31;
    if (w >= ndst) return;
    int beg = offs[w], end = offs[w + 1];
    float a[3][4];
#pragma unroll
    for (int t = 0; t < 3; t++)
#pragma unroll
        for (int q = 0; q < 4; q++) a[t][q] = 0.f;
    int j = lane * 4;
    int i = beg;
    for (; i + 1 < end; i += 2) {
        unsigned p0 = (unsigned)__ldg(pay + i);
        unsigned p1 = (unsigned)__ldg(pay + i + 1);
        const fp162* s0 = (const fp162*)(H + (size_t)(p0 & 0x0FFFFFFFu) * 128 + j);
        const fp162* s1 = (const fp162*)(H + (size_t)(p1 & 0x0FFFFFFFu) * 128 + j);
        fp162 u00 = s0[0], u01 = s0[1];
        fp162 u10 = s1[0], u11 = s1[1];
        int t0 = (int)(p0 >> 28), t1 = (int)(p1 >> 28);
        float2 f00 = __half22float2(u00), f01 = __half22float2(u01);
        a[t0][0] += f00.x; a[t0][1] += f00.y; a[t0][2] += f01.x; a[t0][3] += f01.y;
        float2 f10 = __half22float2(u10), f11 = __half22float2(u11);
        a[t1][0] += f10.x; a[t1][1] += f10.y; a[t1][2] += f11.x; a[t1][3] += f11.y;
    }
    if (i < end) {
        unsigned p = (unsigned)__ldg(pay + i);
        const fp162* s = (const fp162*)(H + (size_t)(p & 0x0FFFFFFFu) * 128 + j);
        float2 f0 = __half22float2(s[0]);
        float2 f1 = __half22float2(s[1]);
        int t = (int)(p >> 28);
        a[t][0] += f0.x; a[t][1] += f0.y; a[t][2] += f1.x; a[t][3] += f1.y;
    }
    size_t base = (size_t)w * KAGG;
#pragma unroll
    for (int t = 0; t < 3; t++) {
        fp162* dst = (fp162*)(AGG + base + t * 128 + j);
        dst[0] = __floats2half2_rn(a[t][0], a[t][1]);
        dst[1] = __floats2half2_rn(a[t][2], a[t][3]);
    }
    // pad + deg cols written once at setup (round-invariant)
}

// ------------------------- cp.async helpers -------------------------
__device__ __forceinline__ void cp16(uint32_t dst, const void* src, int sz) {
    asm volatile("cp.async.cg.shared.global [%0], [%1], 16, %2;" :: "r"(dst), "l"(src), "r"(sz));
}
__device__ __forceinline__ void cp_commit() { asm volatile("cp.async.commit_group;"); }
__device__ __forceinline__ void cp_wait0() { asm volatile("cp.async.wait_group 0;"); }
__device__ __forceinline__ void cp_wait1() { asm volatile("cp.async.wait_group 1;"); }

__device__ __forceinline__ void ldm_x4(uint32_t addr, uint32_t& r0, uint32_t& r1, uint32_t& r2, uint32_t& r3) {
    asm volatile("ldmatrix.sync.aligned.m8n8.x4.shared.b16 {%0,%1,%2,%3}, [%4];"
                 : "=r"(r0), "=r"(r1), "=r"(r2), "=r"(r3) : "r"(addr));
}

#define MMA16(d, a, b)                                                                             \
    asm volatile("mma.sync.aligned.m16n8k16.row.col.f32.f16.f16.f32 "                             \
                 "{%0,%1,%2,%3},{%4,%5,%6,%7},{%8,%9},{%0,%1,%2,%3};"                             \
                 : "+f"(d[0]), "+f"(d[1]), "+f"(d[2]), "+f"(d[3])                                  \
                 : "r"(a[0]), "r"(a[1]), "r"(a[2]), "r"(a[3]), "r"(b[0]), "r"(b[1]))

// smem geometry (halves)
#define MM_STR 40
#define MM_STAGE_HALVES (128 * MM_STR)
#define MM_SMEM_HALVES  (3 * 2 * MM_STAGE_HALVES)
#define MM_SMEM_BYTES   (MM_SMEM_HALVES * 2)             // 61440

// ------------------------- unified fp16 tensor-core GEMM -------------------------
// 256 threads, 8 warps, warp tile 32x64 (champion geometry).
// Y[M,N] = X[M,K] @ W[N,K]^T (+ bias)
// XMODE: 0 plain (stride=K), 1 [MSG|Ch], 2 [MSG|flip|H], 3 [L[:NV]|L[NV:]]
// EPI:   0 bias-store, 1 bias-relu-store, 2 fused LSTM cell (gate-permuted weights, fp16 c)
// GSWAP: 1 -> (m,n)=(by,bx): n-blocks schedule-adjacent for L2 X reuse
// 3-stage cp.async ring, ONE __syncthreads per K-iter.
template <int XMODE, int EPI, int K, int GSWAP>
__global__ void __launch_bounds__(256, 2) mm_kernel(
    const fp16* __restrict__ X0, const fp16* __restrict__ X1,
    const fp16* __restrict__ W, const float* __restrict__ bias,
    fp16* __restrict__ Y, int ldY,
    const fp16* __restrict__ Cold, fp16* __restrict__ Hnew, fp16* __restrict__ Cnew,
    int M) {
    extern __shared__ __align__(16) fp16 smraw[];
    fp16* xs = smraw;                          // [3][128][MM_STR]
    fp16* ws = smraw + 3 * MM_STAGE_HALVES;    // [3][128][MM_STR]
    const int tid = threadIdx.x;
    const int lane = tid & 31, warp = tid >> 5;
    const int wm = warp & 3, wn = warp >> 2;
    const int mblk = GSWAP ? blockIdx.y : blockIdx.x;
    const int nblk = GSWAP ? blockIdx.x : blockIdx.y;
    const int row0 = mblk * 128, n0 = nblk * 128;
    const uint32_t xs_u = (uint32_t)__cvta_generic_to_shared(xs);
    const uint32_t ws_u = (uint32_t)__cvta_generic_to_shared(ws);

    float acc[2][8][4];
#pragma unroll
    for (int a = 0; a < 2; a++)
#pragma unroll
        for (int b = 0; b < 8; b++)
#pragma unroll
            for (int c = 0; c < 4; c++) acc[a][b][c] = 0.0f;

    auto load_tiles = [&](int it, int buf) {
        int kb = it * 32;
        uint32_t xbase = xs_u + (uint32_t)(buf * MM_STAGE_HALVES * 2);
        uint32_t wbase = ws_u + (uint32_t)(buf * MM_STAGE_HALVES * 2);
#pragma unroll
        for (int q = 0; q < 2; q++) {
            int chunk = tid + 256 * q;
            int r = chunk >> 2, cc = chunk & 3;
            int gr = row0 + r;
            int grc = gr < M ? gr : (M - 1);
            int gk = kb + cc * 8;
            const fp16* src;
            if (XMODE == 0) {
                src = X0 + (size_t)grc * K + gk;
            } else if (XMODE == 1) {
                src = (gk < 128) ? X0 + (size_t)grc * 128 + gk
                                 : X1 + (size_t)grc * 128 + (gk - 128);
            } else if (XMODE == 2) {
                if (gk < 128) src = X0 + (size_t)grc * 128 + gk;
                else if (gk < 256) {
                    int fr = (grc < NV) ? grc + NV : grc - NV;
                    src = X1 + (size_t)fr * 128 + (gk - 128);
                } else src = X1 + (size_t)grc * 128 + (gk - 256);
            } else {  // XMODE 3
                src = (gk < 128) ? X0 + (size_t)grc * 128 + gk
                                 : X0 + (size_t)(grc + NV) * 128 + (gk - 128);
            }
            cp16(xbase + (uint32_t)((r * MM_STR + cc * 8) * 2), src, gr < M ? 16 : 0);
        }
#pragma unroll
        for (int q = 0; q < 2; q++) {
            int chunk = tid + 256 * q;
            int n = chunk >> 2, cc = chunk & 3;
            const fp16* src = W + (size_t)(n0 + n) * K + kb + cc * 8;
            cp16(wbase + (uint32_t)((n * MM_STR + cc * 8) * 2), src, 16);
        }
        cp_commit();
    };

    auto compute = [&](int buf) {
        uint32_t xbase = xs_u + (uint32_t)(buf * MM_STAGE_HALVES * 2);
        uint32_t wbase = ws_u + (uint32_t)(buf * MM_STAGE_HALVES * 2);
#pragma unroll
        for (int ks = 0; ks < 2; ks++) {
            int coloff = ks * 16 + ((lane >> 4) & 1) * 8;
            uint32_t afrag[2][4];
#pragma unroll
            for (int mt = 0; mt < 2; mt++) {
                int r = wm * 32 + mt * 16 + (lane & 15);
                uint32_t addr = xbase + (uint32_t)((r * MM_STR + coloff) * 2);
                ldm_x4(addr, afrag[mt][0], afrag[mt][1], afrag[mt][2], afrag[mt][3]);
            }
            uint32_t bfrag[8][2];
#pragma unroll
            for (int p = 0; p < 4; p++) {
                int n = wn * 64 + p * 16 + (lane & 15);
                uint32_t addr = wbase + (uint32_t)((n * MM_STR + coloff) * 2);
                uint32_t r0, r1, r2, r3;
                ldm_x4(addr, r0, r1, r2, r3);
                bfrag[2 * p][0] = r0; bfrag[2 * p][1] = r2;
                bfrag[2 * p + 1][0] = r1; bfrag[2 * p + 1][1] = r3;
            }
#pragma unroll
            for (int mt = 0; mt < 2; mt++)
#pragma unroll
                for (int nt = 0; nt < 8; nt++) MMA16(acc[mt][nt], afrag[mt], bfrag[nt]);
        }
    };

    constexpr int ITERS = K / 32;
    load_tiles(0, 0);
    load_tiles(1, 1);
    for (int it = 0; it < ITERS; it++) {
        if (it + 1 < ITERS) cp_wait1(); else cp_wait0();
        __syncthreads();
        if (it + 2 < ITERS) load_tiles(it + 2, (it + 2) % 3);
        compute(it % 3);
    }
    __syncthreads();   // protect epilogue smem reuse from lagging warps

    if (EPI == 0 || EPI == 1) {
#pragma unroll
        for (int mt = 0; mt < 2; mt++) {
#pragma unroll
            for (int nt = 0; nt < 8; nt++) {
                int gr0 = row0 + wm * 32 + mt * 16 + (lane >> 2);
                int col = n0 + wn * 64 + nt * 8 + 2 * (lane & 3);
                float b0v = __ldg(bias + col), b1v = __ldg(bias + col + 1);
                float v0 = acc[mt][nt][0] + b0v, v1 = acc[mt][nt][1] + b1v;
                float v2 = acc[mt][nt][2] + b0v, v3 = acc[mt][nt][3] + b1v;
                if (EPI == 1) {
                    v0 = fmaxf(v0, 0.f); v1 = fmaxf(v1, 0.f);
                    v2 = fmaxf(v2, 0.f); v3 = fmaxf(v3, 0.f);
                }
                if (gr0 < M)
                    *(fp162*)(Y + (size_t)gr0 * ldY + col) = __floats2half2_rn(v0, v1);
                if (gr0 + 8 < M)
                    *(fp162*)(Y + (size_t)(gr0 + 8) * ldY + col) = __floats2half2_rn(v2, v3);
            }
        }
    } else {
        // fused LSTM epilogue; this block handles kk in [nblk*32, +32); fp16 cell state
        const int kk0 = nblk * 32;
        float* cs = (float*)smraw;        // [128][33]
        float* hs = cs + 128 * 33;        // [128][33]
        for (int i = tid; i < 1024; i += 256) {
            int r = i >> 3, c = (i & 7) * 4;
            int gr = row0 + r;
            if (gr < M) {
                const fp162* cp = (const fp162*)(Cold + (size_t)gr * 128 + kk0 + c);
                float2 va = __half22float2(cp[0]);
                float2 vb = __half22float2(cp[1]);
                cs[r * 33 + c + 0] = va.x; cs[r * 33 + c + 1] = va.y;
                cs[r * 33 + c + 2] = vb.x; cs[r * 33 + c + 3] = vb.y;
            }
        }
        __syncthreads();
        const int odd = lane & 1;
#pragma unroll
        for (int nt = 0; nt < 8; nt++) {
            int colp = wn * 64 + nt * 8 + 2 * (lane & 3);
            float b0v = __ldg(bias + n0 + colp), b1v = __ldg(bias + n0 + colp + 1);
            int kkl = colp >> 2;
#pragma unroll
            for (int mt = 0; mt < 2; mt++) {
                float c0 = acc[mt][nt][0] + b0v, c1 = acc[mt][nt][1] + b1v;
                float c2 = acc[mt][nt][2] + b0v, c3 = acc[mt][nt][3] + b1v;
                float x0 = __shfl_xor_sync(0xffffffffu, c0, 1);
                float x1 = __shfl_xor_sync(0xffffffffu, c1, 1);
                float x2 = __shfl_xor_sync(0xffffffffu, c2, 1);
                float x3 = __shfl_xor_sync(0xffffffffu, c3, 1);
                float gi = odd ? x2 : c0;
                float gf = odd ? x3 : c1;
                float gg = odd ? c2 : x0;
                float go = odd ? c3 : x1;
                int rloc = wm * 32 + mt * 16 + (lane >> 2) + odd * 8;
                float cold = cs[rloc * 33 + kkl];
                float c2v = sigmoid_fast(gf) * cold + sigmoid_fast(gi) * tanh_fast(gg);
                float h = sigmoid_fast(go) * tanh_fast(c2v);
                cs[rloc * 33 + kkl] = c2v;
                hs[rloc * 33 + kkl] = h;
            }
        }
        __syncthreads();
        for (int i = tid; i < 1024; i += 256) {
            int r = i >> 3, c = (i & 7) * 4;
            int gr = row0 + r;
            if (gr < M) {
                fp162* cd = (fp162*)(Cnew + (size_t)gr * 128 + kk0 + c);
                cd[0] = __floats2half2_rn(cs[r * 33 + c], cs[r * 33 + c + 1]);
                cd[1] = __floats2half2_rn(cs[r * 33 + c + 2], cs[r * 33 + c + 3]);
                fp162* hp = (fp162*)(Hnew + (size_t)gr * 128 + kk0 + c);
                hp[0] = __floats2half2_rn(hs[r * 33 + c], hs[r * 33 + c + 1]);
                hp[1] = __floats2half2_rn(hs[r * 33 + c + 2], hs[r * 33 + c + 3]);
            }
        }
    }
}

// ------------------------- final vote -------------------------
__global__ void vote_kernel(const fp16* __restrict__ H2, const float* __restrict__ w3,
                            const float* __restrict__ b3, float* __restrict__ out, int M) {
    int w = (blockIdx.x * blockDim.x + threadIdx.x) >> 5;
    int lane = threadIdx.x & 31;
    if (w < M) {
        float s = 0.0f;
#pragma unroll
        for (int q = 0; q < 4; q++) {
            int j = lane + 32 * q;
            s += __half2float(H2[(size_t)w * 128 + j]) * __ldg(w3 + j);
        }
#pragma unroll
        for (int o = 16; o > 0; o >>= 1) s += __shfl_xor_sync(0xffffffffu, s, o);
        if (lane == 0) out[w] = s + b3[0];
    }
}

// ------------------------- host orchestration -------------------------
static void build_csr(const int* src0, const int* dst0, int E0,
                      const int* src1, const int* dst1, int E1,
                      const int* src2, const int* dst2, int E2,
                      int ndst, int* offs, int* pay,
                      int* cnt, int* cur, int* exsc, int* blksum) {
    zero_int_kernel<<<(ndst + 255) / 256, 256>>>(cnt, ndst);
    hist_kernel<<<(E0 + 255) / 256, 256>>>(dst0, E0, cnt);
    hist_kernel<<<(E1 + 255) / 256, 256>>>(dst1, E1, cnt);
    hist_kernel<<<(E2 + 255) / 256, 256>>>(dst2, E2, cnt);
    int nb = (ndst + 1023) / 1024;
    scanA_kernel<<<nb, 1024>>>(cnt, exsc, blksum, ndst);
    scanB_kernel<<<1, 32>>>(blksum, nb);
    scanC_kernel<<<(ndst + 255) / 256, 256>>>(exsc, blksum, offs, ndst, E0 + E1 + E2);
    zero_int_kernel<<<(ndst + 255) / 256, 256>>>(cur, ndst);
    fill_csr_kernel<<<(E0 + 255) / 256, 256>>>(src0, dst0, E0, 0, offs, cur, pay);
    fill_csr_kernel<<<(E1 + 255) / 256, 256>>>(src1, dst1, E1, 1, offs, cur, pay);
    fill_csr_kernel<<<(E2 + 255) / 256, 256>>>(src2, dst2, E2, 2, offs, cur, pay);
}

extern "C" void kernel_launch(void* const* d_in, const int* in_sizes, int n_in,
                              void* d_out, int out_size) {
    (void)in_sizes; (void)n_in; (void)out_size;
    const float* l_init_w   = (const float*)d_in[0];
    const float* l_init_b   = (const float*)d_in[1];
    const float* c_init_w   = (const float*)d_in[2];
    const float* c_init_b   = (const float*)d_in[3];
    const float* mha_in_w   = (const float*)d_in[4];
    const float* mha_in_b   = (const float*)d_in[5];
    const float* mha_out_w  = (const float*)d_in[6];
    const float* mha_out_b  = (const float*)d_in[7];
    const float* lstm_L_wih = (const float*)d_in[8];
    const float* lstm_L_whh = (const float*)d_in[9];
    const float* lstm_L_bih = (const float*)d_in[10];
    const float* lstm_L_bhh = (const float*)d_in[11];
    const float* lstm_C_wih = (const float*)d_in[12];
    const float* lstm_C_whh = (const float*)d_in[13];
    const float* lstm_C_bih = (const float*)d_in[14];
    const float* lstm_C_bhh = (const float*)d_in[15];
    const float* mlp_w1     = (const float*)d_in[16];
    const float* mlp_b1     = (const float*)d_in[17];
    const float* mlp_w2     = (const float*)d_in[18];
    const float* mlp_b2     = (const float*)d_in[19];
    const float* mlp_w3     = (const float*)d_in[20];
    const float* mlp_b3     = (const float*)d_in[21];
    const int* child_lit    = (const int*)d_in[22];
    const int* child_clause = (const int*)d_in[23];
    const int* fa_lit       = (const int*)d_in[24];
    const int* fa_clause    = (const int*)d_in[25];
    const int* nt_lit       = (const int*)d_in[26];
    const int* nt_clause    = (const int*)d_in[27];

    fp16 *Lh0, *Lh1, *Lc, *Ch0, *Ch1, *Cc, *MSG, *G, *AGG, *BIASC, *WgatC, *WcatL, *WC, *WL, *W1, *W2;
    float *Weff, *beff, *bC, *bL, *zeroB;
    int *offsLC, *offsCL, *payLC, *payCL, *cnt, *cur, *exsc, *blksum;
    cudaGetSymbolAddress((void**)&Lh0, g_Lh0);
    cudaGetSymbolAddress((void**)&Lh1, g_Lh1);
    cudaGetSymbolAddress((void**)&Lc,  g_Lc);
    cudaGetSymbolAddress((void**)&Ch0, g_Ch0);
    cudaGetSymbolAddress((void**)&Ch1, g_Ch1);
    cudaGetSymbolAddress((void**)&Cc,  g_Cc);
    cudaGetSymbolAddress((void**)&MSG, g_MSG);
    cudaGetSymbolAddress((void**)&G,   g_G);
    cudaGetSymbolAddress((void**)&AGG, g_AGG);
    cudaGetSymbolAddress((void**)&BIASC, g_BIASC);
    cudaGetSymbolAddress((void**)&Weff, g_Weff);
    cudaGetSymbolAddress((void**)&beff, g_beff);
    cudaGetSymbolAddress((void**)&WgatC, g_WgatC);
    cudaGetSymbolAddress((void**)&WcatL, g_WcatL);
    cudaGetSymbolAddress((void**)&WC, g_WC);
    cudaGetSymbolAddress((void**)&bC, g_bC);
    cudaGetSymbolAddress((void**)&WL, g_WL);
    cudaGetSymbolAddress((void**)&bL, g_bL);
    cudaGetSymbolAddress((void**)&W1, g_W1);
    cudaGetSymbolAddress((void**)&W2, g_W2);
    cudaGetSymbolAddress((void**)&zeroB, g_zero);
    cudaGetSymbolAddress((void**)&offsLC, g_offsLC);
    cudaGetSymbolAddress((void**)&offsCL, g_offsCL);
    cudaGetSymbolAddress((void**)&payLC, g_payLC);
    cudaGetSymbolAddress((void**)&payCL, g_payCL);
    cudaGetSymbolAddress((void**)&cnt, g_cnt);
    cudaGetSymbolAddress((void**)&cur, g_cur);
    cudaGetSymbolAddress((void**)&exsc, g_exsc);
    cudaGetSymbolAddress((void**)&blksum, g_blksum);

    cudaFuncSetAttribute(mm_kernel<0, 0, 128, 1>, cudaFuncAttributeMaxDynamicSharedMemorySize, MM_SMEM_BYTES);
    cudaFuncSetAttribute(mm_kernel<1, 2, 256, 1>, cudaFuncAttributeMaxDynamicSharedMemorySize, MM_SMEM_BYTES);
    cudaFuncSetAttribute(mm_kernel<0, 0, KAGG, 0>, cudaFuncAttributeMaxDynamicSharedMemorySize, MM_SMEM_BYTES);
    cudaFuncSetAttribute(mm_kernel<2, 2, 384, 1>, cudaFuncAttributeMaxDynamicSharedMemorySize, MM_SMEM_BYTES);
    cudaFuncSetAttribute(mm_kernel<3, 1, 256, 0>, cudaFuncAttributeMaxDynamicSharedMemorySize, MM_SMEM_BYTES);
    cudaFuncSetAttribute(mm_kernel<0, 1, 128, 0>, cudaFuncAttributeMaxDynamicSharedMemorySize, MM_SMEM_BYTES);

    // ---- setup ----
    compute_weff_kernel<<<dim3(128, 6), 128>>>(mha_in_w, mha_in_b, mha_out_w, mha_out_b, Weff, beff);
    prep_wgat_kernel<<<384, 128>>>(Weff, WgatC);
    prep_wcatL_kernel<<<128, KAGG>>>(Weff, beff, WcatL);
    prep_lstm_kernel<<<512, 256>>>(lstm_C_wih, lstm_C_whh, lstm_C_bih, lstm_C_bhh, WC, bC, 128);
    prep_lstm_kernel<<<512, 384>>>(lstm_L_wih, lstm_L_whh, lstm_L_bih, lstm_L_bhh, WL, bL, 256);
    prep_mlp_kernel<<<(128 * 256 + 255) / 256, 256>>>(mlp_w1, mlp_w2, W1, W2);
    init_state_kernel<<<(int)(((size_t)NC * DIM + 255) / 256), 256>>>(
        l_init_w, l_init_b, c_init_w, c_init_b, Lh0, Lc, Ch0, Cc);

    build_csr(child_lit, child_clause, ECNT, fa_lit, fa_clause, EFNT, nt_lit, nt_clause, ENNT,
              NC, offsLC, payLC, cnt, cur, exsc, blksum);
    build_csr(child_clause, child_lit, ECNT, fa_clause, fa_lit, EFNT, nt_clause, nt_lit, ENNT,
              NL, offsCL, payCL, cnt, cur, exsc, blksum);

    // round-invariant aggregation constants
    prep_biasC_kernel<<<(NC * 32 + 255) / 256, 256>>>(payLC, offsLC, beff, BIASC, NC);
    prep_aggpad_kernel<<<(NL * 32 + 255) / 256, 256>>>(payCL, offsCL, AGG, NL);

    fp16* Lcur = Lh0; fp16* Lnxt = Lh1;
    fp16* Ccur = Ch0; fp16* Cnxt = Ch1;

    const int GB_L = (NL + 127) / 128;   // 782
    const int GB_C = (NC + 127) / 128;   // 1641
    const int GB_V = (NV + 127) / 128;   // 391

    for (int r = 0; r < ROUNDS; r++) {
        // ---- L -> C: transform L (small side), gather-aggregate into MSG ----
        mm_kernel<0, 0, 128, 1><<<dim3(3, GB_L), 256, MM_SMEM_BYTES>>>(
            Lcur, nullptr, WgatC, zeroB, G, 384, nullptr, nullptr, nullptr, NL);
        aggL2C_kernel<<<(NC * 32 + 255) / 256, 256>>>(payLC, offsLC, G, BIASC, MSG, NC);
        mm_kernel<1, 2, 256, 1><<<dim3(4, GB_C), 256, MM_SMEM_BYTES>>>(
            MSG, Ccur, WC, bC, nullptr, 0, Cc, Cnxt, Cc, NC);
        { fp16* t = Ccur; Ccur = Cnxt; Cnxt = t; }

        // ---- C -> L: aggregate C (small dst side), then transform ----
        aggC2L_kernel<<<(NL * 32 + 255) / 256, 256>>>(payCL, offsCL, Ccur, AGG, NL);
        mm_kernel<0, 0, KAGG, 0><<<dim3(GB_L, 1), 256, MM_SMEM_BYTES>>>(
            AGG, nullptr, WcatL, zeroB, MSG, 128, nullptr, nullptr, nullptr, NL);
        mm_kernel<2, 2, 384, 1><<<dim3(4, GB_L), 256, MM_SMEM_BYTES>>>(
            MSG, Lcur, WL, bL, nullptr, 0, Lc, Lnxt, Lc, NL);
        { fp16* t = Lcur; Lcur = Lnxt; Lnxt = t; }
    }

    // ---- final MLP ----
    mm_kernel<3, 1, 256, 0><<<dim3(GB_V, 1), 256, MM_SMEM_BYTES>>>(
        Lcur, nullptr, W1, mlp_b1, G, 128, nullptr, nullptr, nullptr, NV);
    mm_kernel<0, 1, 128, 0><<<dim3(GB_V, 1), 256, MM_SMEM_BYTES>>>(
        G, nullptr, W2, mlp_b2, MSG, 128, nullptr, nullptr, nullptr, NV);
    vote_kernel<<<(NV * 32 + 255) / 256, 256>>>(MSG, mlp_w3, mlp_b3, (float*)d_out, NV);
}